// round 11
// baseline (speedup 1.0000x reference)
#include <cuda_runtime.h>

#define SEQ     1024
#define HDIM    640
#define G4      2560
#define NNODES  1024
#define NEDGES  16384
#define BSZ     16
#define NCTA_REC 128
#define MAXSPLIT 8
#define SENTINEL_U 0x40000000u   /* 2.0f — impossible for |h|<1 */

// ---------------- scratch (device globals; no runtime allocation) ----------------
__device__ float g_xWp[MAXSPLIT][SEQ * G4]; // 84 MB  split-K partials
__device__ float g_xW[SEQ * G4];            // 10.5 MB reduced LSTM input projections
__device__ float g_bufA[SEQ * HDIM];
__device__ float g_bufB[SEQ * HDIM];
__device__ float g_gh[NNODES * 320];
__device__ float g_gy[NNODES * 320];
__device__ float g_Wt[640 * 320];
__device__ int   g_deg[NNODES];
__device__ float g_dinv[NNODES];
__device__ float g_selfnorm[NNODES];
__device__ float g_enorm[NEDGES];

__device__ __forceinline__ float fsigmoid(float x) { return 1.f / (1.f + __expf(-x)); }
__device__ __forceinline__ float ftanh(float x) { return 2.f / (1.f + __expf(-2.f * x)) - 1.f; }

// ---------------- split-K fp32 NT GEMM: partial C_z = A[:,kz]*B[:,kz]^T ----------------
// BM=128 BN=128 BK=16, 256 threads, 8x8/thread, double-buffered. M%128==0, N%128==0.
__global__ __launch_bounds__(256) void sgemm128_split(
    const float* __restrict__ A, const float* __restrict__ B,
    float* __restrict__ Cbase, int M, int N, int K, int Kc)
{
    __shared__ float As[2][16][128];
    __shared__ float Bs[2][16][128];
    const int tid = threadIdx.x;
    const int z = blockIdx.z;
    const int k0 = z * Kc;
    const int kend = min(K, k0 + Kc);
    float* __restrict__ C = Cbase + (size_t)z * ((size_t)SEQ * G4);
    const int m0 = blockIdx.y * 128, n0 = blockIdx.x * 128;
    const int rowg = (tid >> 4) << 3;
    const int colg = (tid & 15) << 3;

    float acc[8][8];
#pragma unroll
    for (int i = 0; i < 8; i++)
#pragma unroll
        for (int j = 0; j < 8; j++) acc[i][j] = 0.f;

    const int ntiles = (kend - k0 + 15) >> 4;

    auto ldtile = [&](const float* __restrict__ P, int base_row, int kb, float4* out) {
#pragma unroll
        for (int i = 0; i < 2; i++) {
            int fid = tid * 2 + i;
            int r = fid >> 2, kk = (fid & 3) << 2;
            float4 v = make_float4(0.f, 0.f, 0.f, 0.f);
            const float* p = P + (size_t)(base_row + r) * K + kb + kk;
            if (kb + kk + 3 < kend) v = *(const float4*)p;
            else {
                if (kb + kk + 0 < kend) v.x = p[0];
                if (kb + kk + 1 < kend) v.y = p[1];
                if (kb + kk + 2 < kend) v.z = p[2];
            }
            out[i] = v;
        }
    };
    auto sttile = [&](float (*S)[128], const float4* v) {
#pragma unroll
        for (int i = 0; i < 2; i++) {
            int fid = tid * 2 + i;
            int r = fid >> 2, kk = (fid & 3) << 2;
            S[kk + 0][r] = v[i].x; S[kk + 1][r] = v[i].y;
            S[kk + 2][r] = v[i].z; S[kk + 3][r] = v[i].w;
        }
    };

    float4 pa[2], pb[2];
    ldtile(A, m0, k0, pa);
    ldtile(B, n0, k0, pb);
    sttile(As[0], pa);
    sttile(Bs[0], pb);
    __syncthreads();

    for (int kt = 0; kt < ntiles; kt++) {
        const int cur = kt & 1;
        if (kt + 1 < ntiles) {
            ldtile(A, m0, k0 + (kt + 1) * 16, pa);
            ldtile(B, n0, k0 + (kt + 1) * 16, pb);
        }
        const float (*Ac)[128] = As[cur];
        const float (*Bc)[128] = Bs[cur];
#pragma unroll
        for (int k = 0; k < 16; k++) {
            float4 a0 = *(const float4*)&Ac[k][rowg];
            float4 a1 = *(const float4*)&Ac[k][rowg + 4];
            float4 b0 = *(const float4*)&Bc[k][colg];
            float4 b1 = *(const float4*)&Bc[k][colg + 4];
            float a[8]  = {a0.x, a0.y, a0.z, a0.w, a1.x, a1.y, a1.z, a1.w};
            float bb[8] = {b0.x, b0.y, b0.z, b0.w, b1.x, b1.y, b1.z, b1.w};
#pragma unroll
            for (int i = 0; i < 8; i++)
#pragma unroll
                for (int j = 0; j < 8; j++)
                    acc[i][j] += a[i] * bb[j];
        }
        if (kt + 1 < ntiles) {
            sttile(As[1 - cur], pa);
            sttile(Bs[1 - cur], pb);
        }
        __syncthreads();
    }

#pragma unroll
    for (int i = 0; i < 8; i++) {
        const int m = m0 + rowg + i;
        float* cp = C + (size_t)m * N + n0 + colg;
#pragma unroll
        for (int j = 0; j < 8; j++) cp[j] = acc[i][j];
    }
}

// ---------------- sum split partials + fold biases ----------------
__global__ void reduce_splits(const float* __restrict__ bufs, float* __restrict__ C,
                              const float* __restrict__ b1, const float* __restrict__ b2,
                              int s, int N)
{
    int idx = blockIdx.x * blockDim.x + threadIdx.x;
    size_t base = (size_t)idx * 4;
    float4 acc = *(const float4*)(bufs + base);
    for (int i = 1; i < s; i++) {
        float4 v = *(const float4*)(bufs + (size_t)i * ((size_t)SEQ * G4) + base);
        acc.x += v.x; acc.y += v.y; acc.z += v.z; acc.w += v.w;
    }
    int n = (int)(base % (size_t)N);
    float4 u1 = *(const float4*)(b1 + n);
    float4 u2 = *(const float4*)(b2 + n);
    acc.x += u1.x + u2.x; acc.y += u1.y + u2.y;
    acc.z += u1.z + u2.z; acc.w += u1.w + u2.w;
    *(float4*)(C + base) = acc;
}

// ---------------- GCN fp32 NT GEMM with fused self-loop epilogue ----------------
// Writes gh = A·B^T (raw) and gy = selfnorm[m] * gh (scatter-init value) in one pass.
__global__ __launch_bounds__(256) void sgemm_nt_gcn(
    const float* __restrict__ A, const float* __restrict__ B,
    const float* __restrict__ selfnorm,
    float* __restrict__ GH, float* __restrict__ GY, int M, int N, int K)
{
    __shared__ float As[16][128];
    __shared__ float Bs[16][64];
    const int tx = threadIdx.x, ty = threadIdx.y;
    const int tid = ty * 16 + tx;
    const int m0 = blockIdx.y * 128, n0 = blockIdx.x * 64;

    float acc[8][4];
#pragma unroll
    for (int i = 0; i < 8; i++)
#pragma unroll
        for (int j = 0; j < 4; j++) acc[i][j] = 0.f;

    const bool k4ok = ((K & 3) == 0);
    const int ntiles = (K + 15) >> 4;

    for (int kt = 0; kt < ntiles; kt++) {
        const int kb = kt * 16;
#pragma unroll
        for (int i = 0; i < 2; i++) {
            int fid = tid * 2 + i;
            int r = fid >> 2;
            int kk = (fid & 3) << 2;
            float4 v = make_float4(0.f, 0.f, 0.f, 0.f);
            if (m0 + r < M) {
                const float* ap = A + (size_t)(m0 + r) * K + kb + kk;
                if (k4ok && kb + kk + 3 < K) v = *(const float4*)ap;
                else {
                    if (kb + kk + 0 < K) v.x = ap[0];
                    if (kb + kk + 1 < K) v.y = ap[1];
                    if (kb + kk + 2 < K) v.z = ap[2];
                    if (kb + kk + 3 < K) v.w = ap[3];
                }
            }
            As[kk + 0][r] = v.x; As[kk + 1][r] = v.y;
            As[kk + 2][r] = v.z; As[kk + 3][r] = v.w;
        }
        {
            int r = tid >> 2;
            int kk = (tid & 3) << 2;
            float4 v = make_float4(0.f, 0.f, 0.f, 0.f);
            if (n0 + r < N) {
                const float* bp = B + (size_t)(n0 + r) * K + kb + kk;
                if (k4ok && kb + kk + 3 < K) v = *(const float4*)bp;
                else {
                    if (kb + kk + 0 < K) v.x = bp[0];
                    if (kb + kk + 1 < K) v.y = bp[1];
                    if (kb + kk + 2 < K) v.z = bp[2];
                    if (kb + kk + 3 < K) v.w = bp[3];
                }
            }
            Bs[kk + 0][r] = v.x; Bs[kk + 1][r] = v.y;
            Bs[kk + 2][r] = v.z; Bs[kk + 3][r] = v.w;
        }
        __syncthreads();
#pragma unroll
        for (int k = 0; k < 16; k++) {
            float4 b4 = *(const float4*)&Bs[k][tx * 4];
            float4 a0 = *(const float4*)&As[k][ty * 8];
            float4 a1 = *(const float4*)&As[k][ty * 8 + 4];
            float a[8] = {a0.x, a0.y, a0.z, a0.w, a1.x, a1.y, a1.z, a1.w};
            float bb[4] = {b4.x, b4.y, b4.z, b4.w};
#pragma unroll
            for (int i = 0; i < 8; i++)
#pragma unroll
                for (int j = 0; j < 4; j++)
                    acc[i][j] += a[i] * bb[j];
        }
        __syncthreads();
    }
#pragma unroll
    for (int i = 0; i < 8; i++) {
        int m = m0 + ty * 8 + i;
        if (m >= M) continue;
        const float sn = selfnorm[m];
#pragma unroll
        for (int j = 0; j < 4; j++) {
            int n = n0 + tx * 4 + j;
            if (n < N) {
                float v = acc[i][j];
                GH[(size_t)m * N + n] = v;
                GY[(size_t)m * N + n] = sn * v;
            }
        }
    }
}

// ---------------- sentinel fill: seq_out <- 2.0f ----------------
__global__ void fill_sentinel(float* __restrict__ p) {
    int i = blockIdx.x * blockDim.x + threadIdx.x;   // SEQ*HDIM/4 threads
    float4 s = make_float4(2.f, 2.f, 2.f, 2.f);
    ((float4*)p)[i] = s;
}

__device__ __forceinline__ float4 ldv4v(const float* p) {
    float4 v;
    asm volatile("ld.volatile.global.v4.f32 {%0,%1,%2,%3}, [%4];"
                 : "=f"(v.x), "=f"(v.y), "=f"(v.z), "=f"(v.w)
                 : "l"(p) : "memory");
    return v;
}
__device__ __forceinline__ bool ok4(const float4& v) {
    return __float_as_uint(v.x) != SENTINEL_U && __float_as_uint(v.y) != SENTINEL_U &&
           __float_as_uint(v.z) != SENTINEL_U && __float_as_uint(v.w) != SENTINEL_U;
}

// pipelined sentinel poll: keep 2 loads in flight; check the oldest each round.
// Detection granularity ~ loop period (<<~L2 RT) instead of a full serial retry.
__device__ __forceinline__ float4 poll4(const float* p) {
    float4 q0 = ldv4v(p);
    if (ok4(q0)) return q0;           // fast path: data already there
    float4 q1 = ldv4v(p);
    for (;;) {
        float4 q2 = ldv4v(p);
        if (ok4(q0)) return q0;
        q0 = q1; q1 = q2;
    }
}

// ---------------- persistent LSTM recurrence (sentinel-valued h, R9 topology) ----------------
// 128 CTAs x 640 threads. CTA k owns hidden units [5k,5k+5); warp w: unit u=w>>2,
// gate g=w&3, Whh row in registers. |h|<1 strictly, so 2.0f marks "not yet written".
// Producers: st.relaxed.gpu of h is the publication. Consumers: 160 threads stage h
// via pipelined float4 sentinel polls; detection and payload share the round trip.
__global__ __launch_bounds__(640, 1) void lstm_rec(
    const float* __restrict__ xW,   // [1024, 2560] (biases folded in)
    const float* __restrict__ Whh,  // [2560, 640]
    float* __restrict__ seq_out)    // [1024, 640] pre-filled with 2.0f
{
    __shared__ float h_s[640];
    __shared__ float dots[5][4];
    __shared__ float c_s[5];

    const int tid = threadIdx.x;
    const int w = tid >> 5, l = tid & 31;
    const int k = blockIdx.x;
    const int u = w >> 2;
    const int gsel = w & 3;
    const int uglob = 5 * k + u;
    const int row = gsel * 640 + uglob;

    float wreg[20];
    const float* wp = Whh + (size_t)row * 640 + 20 * l;
#pragma unroll
    for (int i = 0; i < 20; i++) wreg[i] = wp[i];
    if (tid < 5) c_s[tid] = 0.f;
    __syncthreads();

    for (int t = 0; t < SEQ; t++) {
        // warp-0 gate lanes prefetch xW operands before the wait (off critical path)
        float xg0 = 0.f, xg1 = 0.f, xg2 = 0.f, xg3 = 0.f;
        if (tid < 5) {
            const float* xwt = xW + (size_t)t * G4 + 5 * k + tid;
            xg0 = __ldg(xwt);
            xg1 = __ldg(xwt + 640);
            xg2 = __ldg(xwt + 1280);
            xg3 = __ldg(xwt + 1920);
        }

        float acc = 0.f;
        if (t > 0) {
            // 160 threads stage h(t-1) via pipelined float4 sentinel polls
            if (tid < 160) {
                float4 hv = poll4(seq_out + (size_t)(t - 1) * 640 + 4 * tid);
                ((float4*)h_s)[tid] = hv;
            }
            __syncthreads();
            const float4* hp = (const float4*)(h_s + 20 * l);
            // two accumulators: halve the FMA dependency chain
            float accA = 0.f, accB = 0.f;
#pragma unroll
            for (int i = 0; i < 5; i += 2) {
                float4 v = hp[i];
                accA += wreg[4 * i + 0] * v.x + wreg[4 * i + 1] * v.y
                      + wreg[4 * i + 2] * v.z + wreg[4 * i + 3] * v.w;
            }
#pragma unroll
            for (int i = 1; i < 5; i += 2) {
                float4 v = hp[i];
                accB += wreg[4 * i + 0] * v.x + wreg[4 * i + 1] * v.y
                      + wreg[4 * i + 2] * v.z + wreg[4 * i + 3] * v.w;
            }
            acc = accA + accB;
        }
#pragma unroll
        for (int off = 16; off > 0; off >>= 1)
            acc += __shfl_down_sync(0xffffffffu, acc, off);
        if (l == 0) dots[u][gsel] = acc;
        __syncthreads();

        if (w == 0 && l < 5) {
            const int uu = l;
            const int ug = 5 * k + uu;
            float gi = xg0 + dots[uu][0];
            float gf = xg1 + dots[uu][1];
            float gg = xg2 + dots[uu][2];
            float go = xg3 + dots[uu][3];
            float iv = fsigmoid(gi);
            float fv = fsigmoid(gf);
            float gv = ftanh(gg);
            float ov = fsigmoid(go);
            float c = fv * c_s[uu] + iv * gv;
            c_s[uu] = c;
            float hv = ov * ftanh(c);
            asm volatile("st.relaxed.gpu.global.f32 [%0], %1;"
                         :: "l"(seq_out + (size_t)t * 640 + ug), "f"(hv) : "memory");
        }
        // non-gate warps park at the next iteration's __syncthreads (after their
        // own poll); h_s/dots rewrites at t+1 happen only after warp 0 passes it.
    }
}

// ---------------- graph prep ----------------
__global__ void zero_deg(int* deg) {
    int i = blockIdx.x * blockDim.x + threadIdx.x;
    if (i < NNODES) deg[i] = 0;
}
__global__ void count_deg(const int* __restrict__ dst, int* deg) {
    int e = blockIdx.x * blockDim.x + threadIdx.x;
    if (e < NEDGES) atomicAdd(&deg[dst[e]], 1);
}
__global__ void finalize_deg(const int* __restrict__ deg, float* dinv, float* selfnorm) {
    int i = blockIdx.x * blockDim.x + threadIdx.x;
    if (i < NNODES) {
        float d = rsqrtf((float)(deg[i] + 1));
        dinv[i] = d;
        selfnorm[i] = d * d;
    }
}
__global__ void edge_norm(const int* __restrict__ src, const int* __restrict__ dst,
                          const float* __restrict__ dinv, float* enorm) {
    int e = blockIdx.x * blockDim.x + threadIdx.x;
    if (e < NEDGES) enorm[e] = dinv[src[e]] * dinv[dst[e]];
}
__global__ void transpose_k(const float* __restrict__ W, float* __restrict__ Wt,
                            int Cin, int Cout) {
    int idx = blockIdx.x * blockDim.x + threadIdx.x;
    if (idx < Cin * Cout) {
        int i = idx / Cout, o = idx % Cout;
        Wt[o * Cin + i] = W[idx];
    }
}

// ---------------- GCN edge scatter ----------------
__global__ void scatter_edges(const float* __restrict__ h, const float* __restrict__ enorm,
                              const int* __restrict__ src, const int* __restrict__ dst,
                              float* __restrict__ y, int C) {
    int idx = blockIdx.x * blockDim.x + threadIdx.x;
    if (idx < NEDGES * C) {
        int e = idx / C, c = idx - e * C;
        atomicAdd(&y[dst[e] * C + c], enorm[e] * h[src[e] * C + c]);
    }
}

// ---------------- bias + leaky + batchnorm (per-column CTA) ----------------
__global__ void bias_leaky_bn(const float* __restrict__ y, const float* __restrict__ b,
                              float* __restrict__ out, int C) {
    const int c = blockIdx.x;
    const int tid = threadIdx.x;
    const float bias = b[c];
    float s = 0.f, sq = 0.f;
    for (int r = tid; r < NNODES; r += 256) {
        float v = y[r * C + c] + bias;
        v = (v > 0.f) ? v : 0.01f * v;
        s += v; sq += v * v;
    }
    __shared__ float rs[256], rq[256];
    rs[tid] = s; rq[tid] = sq;
    __syncthreads();
    for (int o = 128; o > 0; o >>= 1) {
        if (tid < o) { rs[tid] += rs[tid + o]; rq[tid] += rq[tid + o]; }
        __syncthreads();
    }
    float mean = rs[0] * (1.f / NNODES);
    float var = rq[0] * (1.f / NNODES) - mean * mean;
    float rstd = rsqrtf(var + 1e-5f);
    for (int r = tid; r < NNODES; r += 256) {
        float v = y[r * C + c] + bias;
        v = (v > 0.f) ? v : 0.01f * v;
        out[r * C + c] = (v - mean) * rstd;
    }
}

// ---------------- head: segment sum + concat + 3 FC ----------------
__global__ void head_kernel(const float* __restrict__ x,
                            const float* __restrict__ gender, const float* __restrict__ handed,
                            const float* __restrict__ W1, const float* __restrict__ b1,
                            const float* __restrict__ W2, const float* __restrict__ b2,
                            const float* __restrict__ W3, const float* __restrict__ b3,
                            float* __restrict__ out) {
    const int b = blockIdx.x;
    const int tid = threadIdx.x;
    __shared__ float feat[52];
    __shared__ float y1[32], y2[16];
    if (tid < 50) {
        float s = 0.f;
        for (int r = 0; r < 64; r++) s += x[(b * 64 + r) * 50 + tid];
        feat[tid] = s;
    }
    if (tid == 50) feat[50] = gender[b];
    if (tid == 51) feat[51] = handed[b];
    __syncthreads();
    if (tid < 32) {
        float s = b1[tid];
        for (int i = 0; i < 52; i++) s += feat[i] * W1[tid * 52 + i];
        y1[tid] = s;
    }
    __syncthreads();
    if (tid < 16) {
        float s = b2[tid];
        for (int i = 0; i < 32; i++) s += y1[i] * W2[tid * 32 + i];
        y2[tid] = s;
    }
    __syncthreads();
    if (tid == 0) {
        float s = b3[0];
        for (int i = 0; i < 16; i++) s += y2[i] * W3[i];
        out[b] = s;
    }
}

// ---------------- host ----------------
extern "C" void kernel_launch(void* const* d_in, const int* in_sizes, int n_in,
                              void* d_out, int out_size) {
    const float* x_in   = (const float*)d_in[0];
    const int*   eidx   = (const int*)d_in[1];
    const float* gender = (const float*)d_in[2];
    const float* handed = (const float*)d_in[3];
    const float* Wih[3] = {(const float*)d_in[4], (const float*)d_in[8],  (const float*)d_in[12]};
    const float* Whh[3] = {(const float*)d_in[5], (const float*)d_in[9],  (const float*)d_in[13]};
    const float* bih[3] = {(const float*)d_in[6], (const float*)d_in[10], (const float*)d_in[14]};
    const float* bhh[3] = {(const float*)d_in[7], (const float*)d_in[11], (const float*)d_in[15]};
    const float* gcnW[4] = {(const float*)d_in[16], (const float*)d_in[18], (const float*)d_in[20], (const float*)d_in[22]};
    const float* gcnB[4] = {(const float*)d_in[17], (const float*)d_in[19], (const float*)d_in[21], (const float*)d_in[23]};
    const float* fcW[3] = {(const float*)d_in[24], (const float*)d_in[26], (const float*)d_in[28]};
    const float* fcB[3] = {(const float*)d_in[25], (const float*)d_in[27], (const float*)d_in[29]};

    float *xWp, *xW, *bufA, *bufB, *gh, *gy, *Wt, *dinv, *selfnorm, *enorm;
    int* deg;
    cudaGetSymbolAddress((void**)&xWp, g_xWp);
    cudaGetSymbolAddress((void**)&xW, g_xW);
    cudaGetSymbolAddress((void**)&bufA, g_bufA);
    cudaGetSymbolAddress((void**)&bufB, g_bufB);
    cudaGetSymbolAddress((void**)&gh, g_gh);
    cudaGetSymbolAddress((void**)&gy, g_gy);
    cudaGetSymbolAddress((void**)&Wt, g_Wt);
    cudaGetSymbolAddress((void**)&deg, g_deg);
    cudaGetSymbolAddress((void**)&dinv, g_dinv);
    cudaGetSymbolAddress((void**)&selfnorm, g_selfnorm);
    cudaGetSymbolAddress((void**)&enorm, g_enorm);

    const int* src = eidx;
    const int* dst = eidx + NEDGES;
    dim3 tb(16, 16);
    const int nred = (SEQ * G4) / 4 / 256;      // 2560 CTAs
    const int nfill = (SEQ * HDIM) / 4 / 256;   // 640 CTAs

    // ---- LSTM layer 0 (K=8500, split-K s=8, Kc=1064 multiple of 4) ----
    sgemm128_split<<<dim3(G4 / 128, SEQ / 128, 8), 256>>>(x_in, Wih[0], xWp, SEQ, G4, 8500, 1064);
    reduce_splits<<<nred, 256>>>(xWp, xW, bih[0], bhh[0], 8, G4);
    fill_sentinel<<<nfill, 256>>>(bufA);
    lstm_rec<<<NCTA_REC, 640>>>(xW, Whh[0], bufA);

    // ---- LSTM layer 1 (K=640, split-K s=2) ----
    sgemm128_split<<<dim3(G4 / 128, SEQ / 128, 2), 256>>>(bufA, Wih[1], xWp, SEQ, G4, HDIM, 320);
    reduce_splits<<<nred, 256>>>(xWp, xW, bih[1], bhh[1], 2, G4);
    fill_sentinel<<<nfill, 256>>>(bufB);
    lstm_rec<<<NCTA_REC, 640>>>(xW, Whh[1], bufB);

    // ---- LSTM layer 2 ----
    sgemm128_split<<<dim3(G4 / 128, SEQ / 128, 2), 256>>>(bufB, Wih[2], xWp, SEQ, G4, HDIM, 320);
    reduce_splits<<<nred, 256>>>(xWp, xW, bih[2], bhh[2], 2, G4);
    fill_sentinel<<<nfill, 256>>>(bufA);
    lstm_rec<<<NCTA_REC, 640>>>(xW, Whh[2], bufA);

    // ---- graph prep ----
    zero_deg<<<4, 256>>>(deg);
    count_deg<<<NEDGES / 256, 256>>>(dst, deg);
    finalize_deg<<<4, 256>>>(deg, dinv, selfnorm);
    edge_norm<<<NEDGES / 256, 256>>>(src, dst, dinv, enorm);

    // ---- GCN layers (self-loop term fused into GEMM epilogue) ----
    const int cins[4]  = {640, 320, 180, 90};
    const int couts[4] = {320, 180, 90, 50};
    float* xcur = bufA;
    float* xnext = bufB;
    for (int l = 0; l < 4; l++) {
        int Cin = cins[l], Cout = couts[l];
        transpose_k<<<(Cin * Cout + 255) / 256, 256>>>(gcnW[l], Wt, Cin, Cout);
        sgemm_nt_gcn<<<dim3((Cout + 63) / 64, NNODES / 128), tb>>>(xcur, Wt, selfnorm,
                                                                   gh, gy, NNODES, Cout, Cin);
        scatter_edges<<<(NEDGES * Cout + 255) / 256, 256>>>(gh, enorm, src, dst, gy, Cout);
        bias_leaky_bn<<<Cout, 256>>>(gy, gcnB[l], xnext, Cout);
        float* tmp = xcur; xcur = xnext; xnext = tmp;
    }

    // ---- head ----
    head_kernel<<<BSZ, 64>>>(xcur, gender, handed,
                             fcW[0], fcB[0], fcW[1], fcB[1], fcW[2], fcB[2],
                             (float*)d_out);
}

// round 12
// speedup vs baseline: 1.6691x; 1.6691x over previous
#include <cuda_runtime.h>

#define SEQ     1024
#define HDIM    640
#define G4      2560
#define NNODES  1024
#define NEDGES  16384
#define BSZ     16
#define NCTA_REC 128
#define MAXSPLIT 8
#define SENTINEL_U 0x40000000u   /* 2.0f — impossible for |h|<1 */

// ---------------- scratch (device globals; no runtime allocation) ----------------
__device__ float g_xWp[MAXSPLIT][SEQ * G4]; // 84 MB  split-K partials
__device__ float g_xW[SEQ * G4];            // 10.5 MB reduced LSTM input projections
__device__ float g_bufA[SEQ * HDIM];
__device__ float g_bufB[SEQ * HDIM];
__device__ float g_gh[NNODES * 320];
__device__ float g_gy[NNODES * 320];
__device__ float g_Wt[640 * 320];
__device__ int   g_deg[NNODES];
__device__ float g_dinv[NNODES];
__device__ float g_selfnorm[NNODES];
__device__ float g_enorm[NEDGES];

__device__ __forceinline__ float fsigmoid(float x) { return 1.f / (1.f + __expf(-x)); }
__device__ __forceinline__ float ftanh(float x) { return 2.f / (1.f + __expf(-2.f * x)) - 1.f; }

// ---------------- split-K fp32 NT GEMM: partial C_z = A[:,kz]*B[:,kz]^T ----------------
// BM=128 BN=128 BK=16, 256 threads, 8x8/thread, double-buffered. M%128==0, N%128==0.
__global__ __launch_bounds__(256) void sgemm128_split(
    const float* __restrict__ A, const float* __restrict__ B,
    float* __restrict__ Cbase, int M, int N, int K, int Kc)
{
    __shared__ float As[2][16][128];
    __shared__ float Bs[2][16][128];
    const int tid = threadIdx.x;
    const int z = blockIdx.z;
    const int k0 = z * Kc;
    const int kend = min(K, k0 + Kc);
    float* __restrict__ C = Cbase + (size_t)z * ((size_t)SEQ * G4);
    const int m0 = blockIdx.y * 128, n0 = blockIdx.x * 128;
    const int rowg = (tid >> 4) << 3;
    const int colg = (tid & 15) << 3;

    float acc[8][8];
#pragma unroll
    for (int i = 0; i < 8; i++)
#pragma unroll
        for (int j = 0; j < 8; j++) acc[i][j] = 0.f;

    const int ntiles = (kend - k0 + 15) >> 4;

    auto ldtile = [&](const float* __restrict__ P, int base_row, int kb, float4* out) {
#pragma unroll
        for (int i = 0; i < 2; i++) {
            int fid = tid * 2 + i;
            int r = fid >> 2, kk = (fid & 3) << 2;
            float4 v = make_float4(0.f, 0.f, 0.f, 0.f);
            const float* p = P + (size_t)(base_row + r) * K + kb + kk;
            if (kb + kk + 3 < kend) v = *(const float4*)p;
            else {
                if (kb + kk + 0 < kend) v.x = p[0];
                if (kb + kk + 1 < kend) v.y = p[1];
                if (kb + kk + 2 < kend) v.z = p[2];
            }
            out[i] = v;
        }
    };
    auto sttile = [&](float (*S)[128], const float4* v) {
#pragma unroll
        for (int i = 0; i < 2; i++) {
            int fid = tid * 2 + i;
            int r = fid >> 2, kk = (fid & 3) << 2;
            S[kk + 0][r] = v[i].x; S[kk + 1][r] = v[i].y;
            S[kk + 2][r] = v[i].z; S[kk + 3][r] = v[i].w;
        }
    };

    float4 pa[2], pb[2];
    ldtile(A, m0, k0, pa);
    ldtile(B, n0, k0, pb);
    sttile(As[0], pa);
    sttile(Bs[0], pb);
    __syncthreads();

    for (int kt = 0; kt < ntiles; kt++) {
        const int cur = kt & 1;
        if (kt + 1 < ntiles) {
            ldtile(A, m0, k0 + (kt + 1) * 16, pa);
            ldtile(B, n0, k0 + (kt + 1) * 16, pb);
        }
        const float (*Ac)[128] = As[cur];
        const float (*Bc)[128] = Bs[cur];
#pragma unroll
        for (int k = 0; k < 16; k++) {
            float4 a0 = *(const float4*)&Ac[k][rowg];
            float4 a1 = *(const float4*)&Ac[k][rowg + 4];
            float4 b0 = *(const float4*)&Bc[k][colg];
            float4 b1 = *(const float4*)&Bc[k][colg + 4];
            float a[8]  = {a0.x, a0.y, a0.z, a0.w, a1.x, a1.y, a1.z, a1.w};
            float bb[8] = {b0.x, b0.y, b0.z, b0.w, b1.x, b1.y, b1.z, b1.w};
#pragma unroll
            for (int i = 0; i < 8; i++)
#pragma unroll
                for (int j = 0; j < 8; j++)
                    acc[i][j] += a[i] * bb[j];
        }
        if (kt + 1 < ntiles) {
            sttile(As[1 - cur], pa);
            sttile(Bs[1 - cur], pb);
        }
        __syncthreads();
    }

#pragma unroll
    for (int i = 0; i < 8; i++) {
        const int m = m0 + rowg + i;
        float* cp = C + (size_t)m * N + n0 + colg;
#pragma unroll
        for (int j = 0; j < 8; j++) cp[j] = acc[i][j];
    }
}

// ---------------- sum split partials + fold biases ----------------
__global__ void reduce_splits(const float* __restrict__ bufs, float* __restrict__ C,
                              const float* __restrict__ b1, const float* __restrict__ b2,
                              int s, int N)
{
    int idx = blockIdx.x * blockDim.x + threadIdx.x;
    size_t base = (size_t)idx * 4;
    float4 acc = *(const float4*)(bufs + base);
    for (int i = 1; i < s; i++) {
        float4 v = *(const float4*)(bufs + (size_t)i * ((size_t)SEQ * G4) + base);
        acc.x += v.x; acc.y += v.y; acc.z += v.z; acc.w += v.w;
    }
    int n = (int)(base % (size_t)N);
    float4 u1 = *(const float4*)(b1 + n);
    float4 u2 = *(const float4*)(b2 + n);
    acc.x += u1.x + u2.x; acc.y += u1.y + u2.y;
    acc.z += u1.z + u2.z; acc.w += u1.w + u2.w;
    *(float4*)(C + base) = acc;
}

// ---------------- GCN fp32 NT GEMM with fused self-loop epilogue ----------------
// Writes gh = A·B^T (raw) and gy = selfnorm[m] * gh (scatter-init value) in one pass.
__global__ __launch_bounds__(256) void sgemm_nt_gcn(
    const float* __restrict__ A, const float* __restrict__ B,
    const float* __restrict__ selfnorm,
    float* __restrict__ GH, float* __restrict__ GY, int M, int N, int K)
{
    __shared__ float As[16][128];
    __shared__ float Bs[16][64];
    const int tx = threadIdx.x, ty = threadIdx.y;
    const int tid = ty * 16 + tx;
    const int m0 = blockIdx.y * 128, n0 = blockIdx.x * 64;

    float acc[8][4];
#pragma unroll
    for (int i = 0; i < 8; i++)
#pragma unroll
        for (int j = 0; j < 4; j++) acc[i][j] = 0.f;

    const bool k4ok = ((K & 3) == 0);
    const int ntiles = (K + 15) >> 4;

    for (int kt = 0; kt < ntiles; kt++) {
        const int kb = kt * 16;
#pragma unroll
        for (int i = 0; i < 2; i++) {
            int fid = tid * 2 + i;
            int r = fid >> 2;
            int kk = (fid & 3) << 2;
            float4 v = make_float4(0.f, 0.f, 0.f, 0.f);
            if (m0 + r < M) {
                const float* ap = A + (size_t)(m0 + r) * K + kb + kk;
                if (k4ok && kb + kk + 3 < K) v = *(const float4*)ap;
                else {
                    if (kb + kk + 0 < K) v.x = ap[0];
                    if (kb + kk + 1 < K) v.y = ap[1];
                    if (kb + kk + 2 < K) v.z = ap[2];
                    if (kb + kk + 3 < K) v.w = ap[3];
                }
            }
            As[kk + 0][r] = v.x; As[kk + 1][r] = v.y;
            As[kk + 2][r] = v.z; As[kk + 3][r] = v.w;
        }
        {
            int r = tid >> 2;
            int kk = (tid & 3) << 2;
            float4 v = make_float4(0.f, 0.f, 0.f, 0.f);
            if (n0 + r < N) {
                const float* bp = B + (size_t)(n0 + r) * K + kb + kk;
                if (k4ok && kb + kk + 3 < K) v = *(const float4*)bp;
                else {
                    if (kb + kk + 0 < K) v.x = bp[0];
                    if (kb + kk + 1 < K) v.y = bp[1];
                    if (kb + kk + 2 < K) v.z = bp[2];
                    if (kb + kk + 3 < K) v.w = bp[3];
                }
            }
            Bs[kk + 0][r] = v.x; Bs[kk + 1][r] = v.y;
            Bs[kk + 2][r] = v.z; Bs[kk + 3][r] = v.w;
        }
        __syncthreads();
#pragma unroll
        for (int k = 0; k < 16; k++) {
            float4 b4 = *(const float4*)&Bs[k][tx * 4];
            float4 a0 = *(const float4*)&As[k][ty * 8];
            float4 a1 = *(const float4*)&As[k][ty * 8 + 4];
            float a[8] = {a0.x, a0.y, a0.z, a0.w, a1.x, a1.y, a1.z, a1.w};
            float bb[4] = {b4.x, b4.y, b4.z, b4.w};
#pragma unroll
            for (int i = 0; i < 8; i++)
#pragma unroll
                for (int j = 0; j < 4; j++)
                    acc[i][j] += a[i] * bb[j];
        }
        __syncthreads();
    }
#pragma unroll
    for (int i = 0; i < 8; i++) {
        int m = m0 + ty * 8 + i;
        if (m >= M) continue;
        const float sn = selfnorm[m];
#pragma unroll
        for (int j = 0; j < 4; j++) {
            int n = n0 + tx * 4 + j;
            if (n < N) {
                float v = acc[i][j];
                GH[(size_t)m * N + n] = v;
                GY[(size_t)m * N + n] = sn * v;
            }
        }
    }
}

// ---------------- sentinel fill: seq_out <- 2.0f ----------------
__global__ void fill_sentinel(float* __restrict__ p) {
    int i = blockIdx.x * blockDim.x + threadIdx.x;   // SEQ*HDIM/4 threads
    float4 s = make_float4(2.f, 2.f, 2.f, 2.f);
    ((float4*)p)[i] = s;
}

// ---------------- persistent LSTM recurrence (R9 protocol EXACTLY) ----------------
// 128 CTAs x 640 threads. CTA k owns hidden units [5k,5k+5); warp w: unit u=w>>2,
// gate g=w&3, Whh row in registers. |h|<1 strictly, so 2.0f marks "not yet written".
// Producers: st.relaxed.gpu of h is the publication. Consumers: each thread serially
// polls ITS OWN seq_out[t-1][tid] (ld.relaxed.gpu scalar) — detection and payload share
// one L2 round trip, and the serial retry self-throttles to 1 outstanding request per
// poller per RT (calibrated law from R6/R9/R11: polling harder starves the producer).
__global__ __launch_bounds__(640, 1) void lstm_rec(
    const float* __restrict__ xW,   // [1024, 2560] (biases folded in)
    const float* __restrict__ Whh,  // [2560, 640]
    float* __restrict__ seq_out)    // [1024, 640] pre-filled with 2.0f
{
    __shared__ float h_s[640];
    __shared__ float dots[5][4];
    __shared__ float c_s[5];

    const int tid = threadIdx.x;
    const int w = tid >> 5, l = tid & 31;
    const int k = blockIdx.x;
    const int u = w >> 2;
    const int gsel = w & 3;
    const int uglob = 5 * k + u;
    const int row = gsel * 640 + uglob;

    float wreg[20];
    const float* wp = Whh + (size_t)row * 640 + 20 * l;
#pragma unroll
    for (int i = 0; i < 20; i++) wreg[i] = wp[i];
    if (tid < 5) c_s[tid] = 0.f;
    __syncthreads();

    for (int t = 0; t < SEQ; t++) {
        // warp-0 gate lanes prefetch xW operands before the wait (off critical path)
        float xg0 = 0.f, xg1 = 0.f, xg2 = 0.f, xg3 = 0.f;
        if (tid < 5) {
            const float* xwt = xW + (size_t)t * G4 + 5 * k + tid;
            xg0 = __ldg(xwt);
            xg1 = __ldg(xwt + 640);
            xg2 = __ldg(xwt + 1280);
            xg3 = __ldg(xwt + 1920);
        }

        float acc = 0.f;
        if (t > 0) {
            // serial scalar sentinel poll (R9): first load IS the payload load
            const float* hp_g = seq_out + (size_t)(t - 1) * 640 + tid;
            float hv;
            do {
                asm volatile("ld.relaxed.gpu.global.f32 %0, [%1];"
                             : "=f"(hv) : "l"(hp_g) : "memory");
            } while (__float_as_uint(hv) == SENTINEL_U);
            h_s[tid] = hv;
            __syncthreads();
            const float4* hp = (const float4*)(h_s + 20 * l);
            // dual accumulators: halve the FMA dependency chain (register-local)
            float accA = 0.f, accB = 0.f;
#pragma unroll
            for (int i = 0; i < 5; i += 2) {
                float4 v = hp[i];
                accA += wreg[4 * i + 0] * v.x + wreg[4 * i + 1] * v.y
                      + wreg[4 * i + 2] * v.z + wreg[4 * i + 3] * v.w;
            }
#pragma unroll
            for (int i = 1; i < 5; i += 2) {
                float4 v = hp[i];
                accB += wreg[4 * i + 0] * v.x + wreg[4 * i + 1] * v.y
                      + wreg[4 * i + 2] * v.z + wreg[4 * i + 3] * v.w;
            }
            acc = accA + accB;
        }
#pragma unroll
        for (int off = 16; off > 0; off >>= 1)
            acc += __shfl_down_sync(0xffffffffu, acc, off);
        if (l == 0) dots[u][gsel] = acc;
        __syncthreads();

        if (w == 0 && l < 5) {
            const int uu = l;
            const int ug = 5 * k + uu;
            float gi = xg0 + dots[uu][0];
            float gf = xg1 + dots[uu][1];
            float gg = xg2 + dots[uu][2];
            float go = xg3 + dots[uu][3];
            float iv = fsigmoid(gi);
            float fv = fsigmoid(gf);
            float gv = ftanh(gg);
            float ov = fsigmoid(go);
            float c = fv * c_s[uu] + iv * gv;
            c_s[uu] = c;
            float hv = ov * ftanh(c);
            asm volatile("st.relaxed.gpu.global.f32 [%0], %1;"
                         :: "l"(seq_out + (size_t)t * 640 + ug), "f"(hv) : "memory");
        }
        // non-gate warps park at the next iteration's __syncthreads (after their
        // own poll); h_s/dots rewrites at t+1 happen only after warp 0 passes it.
    }
}

// ---------------- graph prep ----------------
__global__ void zero_deg(int* deg) {
    int i = blockIdx.x * blockDim.x + threadIdx.x;
    if (i < NNODES) deg[i] = 0;
}
__global__ void count_deg(const int* __restrict__ dst, int* deg) {
    int e = blockIdx.x * blockDim.x + threadIdx.x;
    if (e < NEDGES) atomicAdd(&deg[dst[e]], 1);
}
__global__ void finalize_deg(const int* __restrict__ deg, float* dinv, float* selfnorm) {
    int i = blockIdx.x * blockDim.x + threadIdx.x;
    if (i < NNODES) {
        float d = rsqrtf((float)(deg[i] + 1));
        dinv[i] = d;
        selfnorm[i] = d * d;
    }
}
__global__ void edge_norm(const int* __restrict__ src, const int* __restrict__ dst,
                          const float* __restrict__ dinv, float* enorm) {
    int e = blockIdx.x * blockDim.x + threadIdx.x;
    if (e < NEDGES) enorm[e] = dinv[src[e]] * dinv[dst[e]];
}
__global__ void transpose_k(const float* __restrict__ W, float* __restrict__ Wt,
                            int Cin, int Cout) {
    int idx = blockIdx.x * blockDim.x + threadIdx.x;
    if (idx < Cin * Cout) {
        int i = idx / Cout, o = idx % Cout;
        Wt[o * Cin + i] = W[idx];
    }
}

// ---------------- GCN edge scatter ----------------
__global__ void scatter_edges(const float* __restrict__ h, const float* __restrict__ enorm,
                              const int* __restrict__ src, const int* __restrict__ dst,
                              float* __restrict__ y, int C) {
    int idx = blockIdx.x * blockDim.x + threadIdx.x;
    if (idx < NEDGES * C) {
        int e = idx / C, c = idx - e * C;
        atomicAdd(&y[dst[e] * C + c], enorm[e] * h[src[e] * C + c]);
    }
}

// ---------------- bias + leaky + batchnorm (per-column CTA) ----------------
__global__ void bias_leaky_bn(const float* __restrict__ y, const float* __restrict__ b,
                              float* __restrict__ out, int C) {
    const int c = blockIdx.x;
    const int tid = threadIdx.x;
    const float bias = b[c];
    float s = 0.f, sq = 0.f;
    for (int r = tid; r < NNODES; r += 256) {
        float v = y[r * C + c] + bias;
        v = (v > 0.f) ? v : 0.01f * v;
        s += v; sq += v * v;
    }
    __shared__ float rs[256], rq[256];
    rs[tid] = s; rq[tid] = sq;
    __syncthreads();
    for (int o = 128; o > 0; o >>= 1) {
        if (tid < o) { rs[tid] += rs[tid + o]; rq[tid] += rq[tid + o]; }
        __syncthreads();
    }
    float mean = rs[0] * (1.f / NNODES);
    float var = rq[0] * (1.f / NNODES) - mean * mean;
    float rstd = rsqrtf(var + 1e-5f);
    for (int r = tid; r < NNODES; r += 256) {
        float v = y[r * C + c] + bias;
        v = (v > 0.f) ? v : 0.01f * v;
        out[r * C + c] = (v - mean) * rstd;
    }
}

// ---------------- head: segment sum + concat + 3 FC ----------------
__global__ void head_kernel(const float* __restrict__ x,
                            const float* __restrict__ gender, const float* __restrict__ handed,
                            const float* __restrict__ W1, const float* __restrict__ b1,
                            const float* __restrict__ W2, const float* __restrict__ b2,
                            const float* __restrict__ W3, const float* __restrict__ b3,
                            float* __restrict__ out) {
    const int b = blockIdx.x;
    const int tid = threadIdx.x;
    __shared__ float feat[52];
    __shared__ float y1[32], y2[16];
    if (tid < 50) {
        float s = 0.f;
        for (int r = 0; r < 64; r++) s += x[(b * 64 + r) * 50 + tid];
        feat[tid] = s;
    }
    if (tid == 50) feat[50] = gender[b];
    if (tid == 51) feat[51] = handed[b];
    __syncthreads();
    if (tid < 32) {
        float s = b1[tid];
        for (int i = 0; i < 52; i++) s += feat[i] * W1[tid * 52 + i];
        y1[tid] = s;
    }
    __syncthreads();
    if (tid < 16) {
        float s = b2[tid];
        for (int i = 0; i < 32; i++) s += y1[i] * W2[tid * 32 + i];
        y2[tid] = s;
    }
    __syncthreads();
    if (tid == 0) {
        float s = b3[0];
        for (int i = 0; i < 16; i++) s += y2[i] * W3[i];
        out[b] = s;
    }
}

// ---------------- host ----------------
extern "C" void kernel_launch(void* const* d_in, const int* in_sizes, int n_in,
                              void* d_out, int out_size) {
    const float* x_in   = (const float*)d_in[0];
    const int*   eidx   = (const int*)d_in[1];
    const float* gender = (const float*)d_in[2];
    const float* handed = (const float*)d_in[3];
    const float* Wih[3] = {(const float*)d_in[4], (const float*)d_in[8],  (const float*)d_in[12]};
    const float* Whh[3] = {(const float*)d_in[5], (const float*)d_in[9],  (const float*)d_in[13]};
    const float* bih[3] = {(const float*)d_in[6], (const float*)d_in[10], (const float*)d_in[14]};
    const float* bhh[3] = {(const float*)d_in[7], (const float*)d_in[11], (const float*)d_in[15]};
    const float* gcnW[4] = {(const float*)d_in[16], (const float*)d_in[18], (const float*)d_in[20], (const float*)d_in[22]};
    const float* gcnB[4] = {(const float*)d_in[17], (const float*)d_in[19], (const float*)d_in[21], (const float*)d_in[23]};
    const float* fcW[3] = {(const float*)d_in[24], (const float*)d_in[26], (const float*)d_in[28]};
    const float* fcB[3] = {(const float*)d_in[25], (const float*)d_in[27], (const float*)d_in[29]};

    float *xWp, *xW, *bufA, *bufB, *gh, *gy, *Wt, *dinv, *selfnorm, *enorm;
    int* deg;
    cudaGetSymbolAddress((void**)&xWp, g_xWp);
    cudaGetSymbolAddress((void**)&xW, g_xW);
    cudaGetSymbolAddress((void**)&bufA, g_bufA);
    cudaGetSymbolAddress((void**)&bufB, g_bufB);
    cudaGetSymbolAddress((void**)&gh, g_gh);
    cudaGetSymbolAddress((void**)&gy, g_gy);
    cudaGetSymbolAddress((void**)&Wt, g_Wt);
    cudaGetSymbolAddress((void**)&deg, g_deg);
    cudaGetSymbolAddress((void**)&dinv, g_dinv);
    cudaGetSymbolAddress((void**)&selfnorm, g_selfnorm);
    cudaGetSymbolAddress((void**)&enorm, g_enorm);

    const int* src = eidx;
    const int* dst = eidx + NEDGES;
    dim3 tb(16, 16);
    const int nred = (SEQ * G4) / 4 / 256;      // 2560 CTAs
    const int nfill = (SEQ * HDIM) / 4 / 256;   // 640 CTAs

    // ---- LSTM layer 0 (K=8500, split-K s=8, Kc=1064 multiple of 4) ----
    sgemm128_split<<<dim3(G4 / 128, SEQ / 128, 8), 256>>>(x_in, Wih[0], xWp, SEQ, G4, 8500, 1064);
    reduce_splits<<<nred, 256>>>(xWp, xW, bih[0], bhh[0], 8, G4);
    fill_sentinel<<<nfill, 256>>>(bufA);
    lstm_rec<<<NCTA_REC, 640>>>(xW, Whh[0], bufA);

    // ---- LSTM layer 1 (K=640, split-K s=2) ----
    sgemm128_split<<<dim3(G4 / 128, SEQ / 128, 2), 256>>>(bufA, Wih[1], xWp, SEQ, G4, HDIM, 320);
    reduce_splits<<<nred, 256>>>(xWp, xW, bih[1], bhh[1], 2, G4);
    fill_sentinel<<<nfill, 256>>>(bufB);
    lstm_rec<<<NCTA_REC, 640>>>(xW, Whh[1], bufB);

    // ---- LSTM layer 2 ----
    sgemm128_split<<<dim3(G4 / 128, SEQ / 128, 2), 256>>>(bufB, Wih[2], xWp, SEQ, G4, HDIM, 320);
    reduce_splits<<<nred, 256>>>(xWp, xW, bih[2], bhh[2], 2, G4);
    fill_sentinel<<<nfill, 256>>>(bufA);
    lstm_rec<<<NCTA_REC, 640>>>(xW, Whh[2], bufA);

    // ---- graph prep ----
    zero_deg<<<4, 256>>>(deg);
    count_deg<<<NEDGES / 256, 256>>>(dst, deg);
    finalize_deg<<<4, 256>>>(deg, dinv, selfnorm);
    edge_norm<<<NEDGES / 256, 256>>>(src, dst, dinv, enorm);

    // ---- GCN layers (self-loop term fused into GEMM epilogue) ----
    const int cins[4]  = {640, 320, 180, 90};
    const int couts[4] = {320, 180, 90, 50};
    float* xcur = bufA;
    float* xnext = bufB;
    for (int l = 0; l < 4; l++) {
        int Cin = cins[l], Cout = couts[l];
        transpose_k<<<(Cin * Cout + 255) / 256, 256>>>(gcnW[l], Wt, Cin, Cout);
        sgemm_nt_gcn<<<dim3((Cout + 63) / 64, NNODES / 128), tb>>>(xcur, Wt, selfnorm,
                                                                   gh, gy, NNODES, Cout, Cin);
        scatter_edges<<<(NEDGES * Cout + 255) / 256, 256>>>(gh, enorm, src, dst, gy, Cout);
        bias_leaky_bn<<<Cout, 256>>>(gy, gcnB[l], xnext, Cout);
        float* tmp = xcur; xcur = xnext; xnext = tmp;
    }

    // ---- head ----
    head_kernel<<<BSZ, 64>>>(xcur, gender, handed,
                             fcW[0], fcB[0], fcW[1], fcB[1], fcW[2], fcB[2],
                             (float*)d_out);
}

// round 13
// speedup vs baseline: 1.8304x; 1.0967x over previous
#include <cuda_runtime.h>

#define SEQ     1024
#define HDIM    640
#define G4      2560
#define NNODES  1024
#define NEDGES  16384
#define BSZ     16
#define NCTA_REC 128
#define MAXSPLIT 8
#define SENTINEL_U 0x40000000u   /* 2.0f — impossible for |h|<1 */

// ---------------- scratch (device globals; no runtime allocation) ----------------
__device__ float g_xWp[MAXSPLIT][SEQ * G4]; // 84 MB  split-K partials
__device__ float g_xW[SEQ * G4];            // 10.5 MB reduced LSTM input projections
__device__ float g_bufA[SEQ * HDIM];
__device__ float g_bufB[SEQ * HDIM];
__device__ float g_comb[SEQ * HDIM * 2];    // float2 {h1(s), h2(s-1)} wavefront channel
__device__ float g_gh[NNODES * 320];
__device__ float g_gy[NNODES * 320];
__device__ float g_Wt[640 * 320];
__device__ int   g_deg[NNODES];
__device__ float g_dinv[NNODES];
__device__ float g_selfnorm[NNODES];
__device__ float g_enorm[NEDGES];

__device__ __forceinline__ float fsigmoid(float x) { return 1.f / (1.f + __expf(-x)); }
__device__ __forceinline__ float ftanh(float x) { return 2.f / (1.f + __expf(-2.f * x)) - 1.f; }

// ---------------- split-K fp32 NT GEMM: partial C_z = A[:,kz]*B[:,kz]^T ----------------
// BM=128 BN=128 BK=16, 256 threads, 8x8/thread, double-buffered. M%128==0, N%128==0.
__global__ __launch_bounds__(256) void sgemm128_split(
    const float* __restrict__ A, const float* __restrict__ B,
    float* __restrict__ Cbase, int M, int N, int K, int Kc)
{
    __shared__ float As[2][16][128];
    __shared__ float Bs[2][16][128];
    const int tid = threadIdx.x;
    const int z = blockIdx.z;
    const int k0 = z * Kc;
    const int kend = min(K, k0 + Kc);
    float* __restrict__ C = Cbase + (size_t)z * ((size_t)SEQ * G4);
    const int m0 = blockIdx.y * 128, n0 = blockIdx.x * 128;
    const int rowg = (tid >> 4) << 3;
    const int colg = (tid & 15) << 3;

    float acc[8][8];
#pragma unroll
    for (int i = 0; i < 8; i++)
#pragma unroll
        for (int j = 0; j < 8; j++) acc[i][j] = 0.f;

    const int ntiles = (kend - k0 + 15) >> 4;

    auto ldtile = [&](const float* __restrict__ P, int base_row, int kb, float4* out) {
#pragma unroll
        for (int i = 0; i < 2; i++) {
            int fid = tid * 2 + i;
            int r = fid >> 2, kk = (fid & 3) << 2;
            float4 v = make_float4(0.f, 0.f, 0.f, 0.f);
            const float* p = P + (size_t)(base_row + r) * K + kb + kk;
            if (kb + kk + 3 < kend) v = *(const float4*)p;
            else {
                if (kb + kk + 0 < kend) v.x = p[0];
                if (kb + kk + 1 < kend) v.y = p[1];
                if (kb + kk + 2 < kend) v.z = p[2];
            }
            out[i] = v;
        }
    };
    auto sttile = [&](float (*S)[128], const float4* v) {
#pragma unroll
        for (int i = 0; i < 2; i++) {
            int fid = tid * 2 + i;
            int r = fid >> 2, kk = (fid & 3) << 2;
            S[kk + 0][r] = v[i].x; S[kk + 1][r] = v[i].y;
            S[kk + 2][r] = v[i].z; S[kk + 3][r] = v[i].w;
        }
    };

    float4 pa[2], pb[2];
    ldtile(A, m0, k0, pa);
    ldtile(B, n0, k0, pb);
    sttile(As[0], pa);
    sttile(Bs[0], pb);
    __syncthreads();

    for (int kt = 0; kt < ntiles; kt++) {
        const int cur = kt & 1;
        if (kt + 1 < ntiles) {
            ldtile(A, m0, k0 + (kt + 1) * 16, pa);
            ldtile(B, n0, k0 + (kt + 1) * 16, pb);
        }
        const float (*Ac)[128] = As[cur];
        const float (*Bc)[128] = Bs[cur];
#pragma unroll
        for (int k = 0; k < 16; k++) {
            float4 a0 = *(const float4*)&Ac[k][rowg];
            float4 a1 = *(const float4*)&Ac[k][rowg + 4];
            float4 b0 = *(const float4*)&Bc[k][colg];
            float4 b1 = *(const float4*)&Bc[k][colg + 4];
            float a[8]  = {a0.x, a0.y, a0.z, a0.w, a1.x, a1.y, a1.z, a1.w};
            float bb[8] = {b0.x, b0.y, b0.z, b0.w, b1.x, b1.y, b1.z, b1.w};
#pragma unroll
            for (int i = 0; i < 8; i++)
#pragma unroll
                for (int j = 0; j < 8; j++)
                    acc[i][j] += a[i] * bb[j];
        }
        if (kt + 1 < ntiles) {
            sttile(As[1 - cur], pa);
            sttile(Bs[1 - cur], pb);
        }
        __syncthreads();
    }

#pragma unroll
    for (int i = 0; i < 8; i++) {
        const int m = m0 + rowg + i;
        float* cp = C + (size_t)m * N + n0 + colg;
#pragma unroll
        for (int j = 0; j < 8; j++) cp[j] = acc[i][j];
    }
}

// ---------------- sum split partials + fold biases ----------------
__global__ void reduce_splits(const float* __restrict__ bufs, float* __restrict__ C,
                              const float* __restrict__ b1, const float* __restrict__ b2,
                              int s, int N)
{
    int idx = blockIdx.x * blockDim.x + threadIdx.x;
    size_t base = (size_t)idx * 4;
    float4 acc = *(const float4*)(bufs + base);
    for (int i = 1; i < s; i++) {
        float4 v = *(const float4*)(bufs + (size_t)i * ((size_t)SEQ * G4) + base);
        acc.x += v.x; acc.y += v.y; acc.z += v.z; acc.w += v.w;
    }
    int n = (int)(base % (size_t)N);
    float4 u1 = *(const float4*)(b1 + n);
    float4 u2 = *(const float4*)(b2 + n);
    acc.x += u1.x + u2.x; acc.y += u1.y + u2.y;
    acc.z += u1.z + u2.z; acc.w += u1.w + u2.w;
    *(float4*)(C + base) = acc;
}

// ---------------- GCN fp32 NT GEMM with fused self-loop epilogue ----------------
__global__ __launch_bounds__(256) void sgemm_nt_gcn(
    const float* __restrict__ A, const float* __restrict__ B,
    const float* __restrict__ selfnorm,
    float* __restrict__ GH, float* __restrict__ GY, int M, int N, int K)
{
    __shared__ float As[16][128];
    __shared__ float Bs[16][64];
    const int tx = threadIdx.x, ty = threadIdx.y;
    const int tid = ty * 16 + tx;
    const int m0 = blockIdx.y * 128, n0 = blockIdx.x * 64;

    float acc[8][4];
#pragma unroll
    for (int i = 0; i < 8; i++)
#pragma unroll
        for (int j = 0; j < 4; j++) acc[i][j] = 0.f;

    const bool k4ok = ((K & 3) == 0);
    const int ntiles = (K + 15) >> 4;

    for (int kt = 0; kt < ntiles; kt++) {
        const int kb = kt * 16;
#pragma unroll
        for (int i = 0; i < 2; i++) {
            int fid = tid * 2 + i;
            int r = fid >> 2;
            int kk = (fid & 3) << 2;
            float4 v = make_float4(0.f, 0.f, 0.f, 0.f);
            if (m0 + r < M) {
                const float* ap = A + (size_t)(m0 + r) * K + kb + kk;
                if (k4ok && kb + kk + 3 < K) v = *(const float4*)ap;
                else {
                    if (kb + kk + 0 < K) v.x = ap[0];
                    if (kb + kk + 1 < K) v.y = ap[1];
                    if (kb + kk + 2 < K) v.z = ap[2];
                    if (kb + kk + 3 < K) v.w = ap[3];
                }
            }
            As[kk + 0][r] = v.x; As[kk + 1][r] = v.y;
            As[kk + 2][r] = v.z; As[kk + 3][r] = v.w;
        }
        {
            int r = tid >> 2;
            int kk = (tid & 3) << 2;
            float4 v = make_float4(0.f, 0.f, 0.f, 0.f);
            if (n0 + r < N) {
                const float* bp = B + (size_t)(n0 + r) * K + kb + kk;
                if (k4ok && kb + kk + 3 < K) v = *(const float4*)bp;
                else {
                    if (kb + kk + 0 < K) v.x = bp[0];
                    if (kb + kk + 1 < K) v.y = bp[1];
                    if (kb + kk + 2 < K) v.z = bp[2];
                    if (kb + kk + 3 < K) v.w = bp[3];
                }
            }
            Bs[kk + 0][r] = v.x; Bs[kk + 1][r] = v.y;
            Bs[kk + 2][r] = v.z; Bs[kk + 3][r] = v.w;
        }
        __syncthreads();
#pragma unroll
        for (int k = 0; k < 16; k++) {
            float4 b4 = *(const float4*)&Bs[k][tx * 4];
            float4 a0 = *(const float4*)&As[k][ty * 8];
            float4 a1 = *(const float4*)&As[k][ty * 8 + 4];
            float a[8] = {a0.x, a0.y, a0.z, a0.w, a1.x, a1.y, a1.z, a1.w};
            float bb[4] = {b4.x, b4.y, b4.z, b4.w};
#pragma unroll
            for (int i = 0; i < 8; i++)
#pragma unroll
                for (int j = 0; j < 4; j++)
                    acc[i][j] += a[i] * bb[j];
        }
        __syncthreads();
    }
#pragma unroll
    for (int i = 0; i < 8; i++) {
        int m = m0 + ty * 8 + i;
        if (m >= M) continue;
        const float sn = selfnorm[m];
#pragma unroll
        for (int j = 0; j < 4; j++) {
            int n = n0 + tx * 4 + j;
            if (n < N) {
                float v = acc[i][j];
                GH[(size_t)m * N + n] = v;
                GY[(size_t)m * N + n] = sn * v;
            }
        }
    }
}

// ---------------- sentinel fill (n4 float4s) ----------------
__global__ void fill_sentinel_n(float* __restrict__ p, int n4) {
    int i = blockIdx.x * blockDim.x + threadIdx.x;
    if (i < n4) ((float4*)p)[i] = make_float4(2.f, 2.f, 2.f, 2.f);
}

// ---------------- persistent LSTM recurrence, single layer (R9 protocol) ----------------
__global__ __launch_bounds__(640, 1) void lstm_rec(
    const float* __restrict__ xW,   // [1024, 2560] (biases folded in)
    const float* __restrict__ Whh,  // [2560, 640]
    float* __restrict__ seq_out)    // [1024, 640] pre-filled with 2.0f
{
    __shared__ float h_s[640];
    __shared__ float dots[5][4];
    __shared__ float c_s[5];

    const int tid = threadIdx.x;
    const int w = tid >> 5, l = tid & 31;
    const int k = blockIdx.x;
    const int u = w >> 2;
    const int gsel = w & 3;
    const int uglob = 5 * k + u;
    const int row = gsel * 640 + uglob;

    float wreg[20];
    const float* wp = Whh + (size_t)row * 640 + 20 * l;
#pragma unroll
    for (int i = 0; i < 20; i++) wreg[i] = wp[i];
    if (tid < 5) c_s[tid] = 0.f;
    __syncthreads();

    for (int t = 0; t < SEQ; t++) {
        float xg0 = 0.f, xg1 = 0.f, xg2 = 0.f, xg3 = 0.f;
        if (tid < 5) {
            const float* xwt = xW + (size_t)t * G4 + 5 * k + tid;
            xg0 = __ldg(xwt);
            xg1 = __ldg(xwt + 640);
            xg2 = __ldg(xwt + 1280);
            xg3 = __ldg(xwt + 1920);
        }

        float acc = 0.f;
        if (t > 0) {
            const float* hp_g = seq_out + (size_t)(t - 1) * 640 + tid;
            float hv;
            do {
                asm volatile("ld.relaxed.gpu.global.f32 %0, [%1];"
                             : "=f"(hv) : "l"(hp_g) : "memory");
            } while (__float_as_uint(hv) == SENTINEL_U);
            h_s[tid] = hv;
            __syncthreads();
            const float4* hp = (const float4*)(h_s + 20 * l);
            float accA = 0.f, accB = 0.f;
#pragma unroll
            for (int i = 0; i < 5; i += 2) {
                float4 v = hp[i];
                accA += wreg[4 * i + 0] * v.x + wreg[4 * i + 1] * v.y
                      + wreg[4 * i + 2] * v.z + wreg[4 * i + 3] * v.w;
            }
#pragma unroll
            for (int i = 1; i < 5; i += 2) {
                float4 v = hp[i];
                accB += wreg[4 * i + 0] * v.x + wreg[4 * i + 1] * v.y
                      + wreg[4 * i + 2] * v.z + wreg[4 * i + 3] * v.w;
            }
            acc = accA + accB;
        }
#pragma unroll
        for (int off = 16; off > 0; off >>= 1)
            acc += __shfl_down_sync(0xffffffffu, acc, off);
        if (l == 0) dots[u][gsel] = acc;
        __syncthreads();

        if (w == 0 && l < 5) {
            const int uu = l;
            const int ug = 5 * k + uu;
            float gi = xg0 + dots[uu][0];
            float gf = xg1 + dots[uu][1];
            float gg = xg2 + dots[uu][2];
            float go = xg3 + dots[uu][3];
            float iv = fsigmoid(gi);
            float fv = fsigmoid(gf);
            float gv = ftanh(gg);
            float ov = fsigmoid(go);
            float c = fv * c_s[uu] + iv * gv;
            c_s[uu] = c;
            float hv = ov * ftanh(c);
            asm volatile("st.relaxed.gpu.global.f32 [%0], %1;"
                         :: "l"(seq_out + (size_t)t * 640 + ug), "f"(hv) : "memory");
        }
    }
}

// ---------------- wavefront recurrence: layers 1 and 2 pipelined ----------------
// At wavefront step s (0..SEQ): L1 computes h1(s) (s<SEQ), L2 computes h2(s-1) (s>=1).
// Channel: comb[s][j] = float2{ h1(s)[j], h2(s-1)[j] } — ONE 8B volatile v2 poll per
// thread per step (same request count as R9's proven protocol). h2(-1)=0 flows through
// Whh2·0 naturally. h2 also stored plainly to h2out for the GCN stage.
// Warp w holds register slices of Whh1[row], Wih2[row], Whh2[row] (row = (w&3)*640+5k+(w>>2));
// L2's gate preactivation = Wih2·h1(s-1) + Whh2·h2(s-2) + bias2 (its GEMM is eliminated).
__global__ __launch_bounds__(640, 1) void lstm_wave12(
    const float* __restrict__ xW1,   // [1024,2560] layer-1 input projection (biases folded)
    const float* __restrict__ Whh1,  // [2560,640]
    const float* __restrict__ Wih2,  // [2560,640]
    const float* __restrict__ Whh2,  // [2560,640]
    const float* __restrict__ bih2, const float* __restrict__ bhh2,
    float* __restrict__ comb,        // [1024*640] float2, sentinel-filled
    float* __restrict__ h2out)       // [1024,640] plain layer-2 output
{
    __shared__ float h1_s[640];
    __shared__ float h2_s[640];
    __shared__ float dots1[5][4];
    __shared__ float dots2[5][4];

    const int tid = threadIdx.x;
    const int w = tid >> 5, l = tid & 31;
    const int k = blockIdx.x;
    const int u = w >> 2;
    const int gsel = w & 3;
    const int uglob = 5 * k + u;
    const int row = gsel * 640 + uglob;

    float wr1[20], wrI[20], wrH[20];
    {
        const float* p1 = Whh1 + (size_t)row * 640 + 20 * l;
        const float* p2 = Wih2 + (size_t)row * 640 + 20 * l;
        const float* p3 = Whh2 + (size_t)row * 640 + 20 * l;
#pragma unroll
        for (int i = 0; i < 20; i++) wr1[i] = p1[i];
#pragma unroll
        for (int i = 0; i < 20; i++) wrI[i] = p2[i];
#pragma unroll
        for (int i = 0; i < 20; i++) wrH[i] = p3[i];
    }

    // lane-register states: c1 in lanes 0-4, c2/h2val in lanes 8-12 of warp 0
    float c1 = 0.f, c2 = 0.f, h2val = 0.f;
    float b2r0 = 0.f, b2r1 = 0.f, b2r2 = 0.f, b2r3 = 0.f;
    if (w == 0 && l >= 8 && l < 13) {
        int ug = 5 * k + (l - 8);
        b2r0 = bih2[ug]        + bhh2[ug];
        b2r1 = bih2[640 + ug]  + bhh2[640 + ug];
        b2r2 = bih2[1280 + ug] + bhh2[1280 + ug];
        b2r3 = bih2[1920 + ug] + bhh2[1920 + ug];
    }
    __syncthreads();

    for (int s = 0; s <= SEQ; s++) {
        // L1 gate lanes prefetch xW1 operands (off critical path)
        float xg0 = 0.f, xg1 = 0.f, xg2 = 0.f, xg3 = 0.f;
        if (tid < 5 && s < SEQ) {
            const float* xwt = xW1 + (size_t)s * G4 + 5 * k + tid;
            xg0 = __ldg(xwt);
            xg1 = __ldg(xwt + 640);
            xg2 = __ldg(xwt + 1280);
            xg3 = __ldg(xwt + 1920);
        }

        float acc1 = 0.f, acc2 = 0.f;
        if (s > 0) {
            // single float2 sentinel poll per thread (R9-calibrated density)
            const float* cp = comb + ((size_t)(s - 1) * 640 + tid) * 2;
            float hx, hy;
            do {
                asm volatile("ld.volatile.global.v2.f32 {%0,%1}, [%2];"
                             : "=f"(hx), "=f"(hy) : "l"(cp) : "memory");
            } while (__float_as_uint(hx) == SENTINEL_U ||
                     __float_as_uint(hy) == SENTINEL_U);
            h1_s[tid] = hx;
            h2_s[tid] = hy;
            __syncthreads();
            const float4* p1 = (const float4*)(h1_s + 20 * l);
            const float4* p2 = (const float4*)(h2_s + 20 * l);
#pragma unroll
            for (int i = 0; i < 5; i++) {
                float4 v1 = p1[i];
                float4 v2 = p2[i];
                acc1 += wr1[4 * i + 0] * v1.x + wr1[4 * i + 1] * v1.y
                      + wr1[4 * i + 2] * v1.z + wr1[4 * i + 3] * v1.w;
                acc2 += wrI[4 * i + 0] * v1.x + wrI[4 * i + 1] * v1.y
                      + wrI[4 * i + 2] * v1.z + wrI[4 * i + 3] * v1.w
                      + wrH[4 * i + 0] * v2.x + wrH[4 * i + 1] * v2.y
                      + wrH[4 * i + 2] * v2.z + wrH[4 * i + 3] * v2.w;
            }
        }
#pragma unroll
        for (int off = 16; off > 0; off >>= 1) {
            acc1 += __shfl_down_sync(0xffffffffu, acc1, off);
            acc2 += __shfl_down_sync(0xffffffffu, acc2, off);
        }
        if (l == 0) { dots1[u][gsel] = acc1; dots2[u][gsel] = acc2; }
        __syncthreads();

        if (w == 0) {
            float h1val = 0.f;
            if (l < 5 && s < SEQ) {               // L1 gates: h1(s)
                const int uu = l;
                float gi = xg0 + dots1[uu][0];
                float gf = xg1 + dots1[uu][1];
                float gg = xg2 + dots1[uu][2];
                float go = xg3 + dots1[uu][3];
                float iv = fsigmoid(gi);
                float fv = fsigmoid(gf);
                float gv = ftanh(gg);
                float ov = fsigmoid(go);
                c1 = fv * c1 + iv * gv;
                h1val = ov * ftanh(c1);
            }
            if (l >= 8 && l < 13 && s >= 1) {     // L2 gates: h2(s-1)
                const int uu = l - 8;
                const int ug = 5 * k + uu;
                float gi = b2r0 + dots2[uu][0];
                float gf = b2r1 + dots2[uu][1];
                float gg = b2r2 + dots2[uu][2];
                float go = b2r3 + dots2[uu][3];
                float iv = fsigmoid(gi);
                float fv = fsigmoid(gf);
                float gv = ftanh(gg);
                float ov = fsigmoid(go);
                c2 = fv * c2 + iv * gv;
                h2val = ov * ftanh(c2);
                h2out[(size_t)(s - 1) * 640 + ug] = h2val;   // plain store for GCN
            }
            // lanes 0-4 fetch h2(s-1) from lanes 8-12 (h2val=0 before L2 activates)
            float h2sh = __shfl_sync(0xffffffffu, h2val, (l + 8) & 31);
            if (l < 5 && s < SEQ) {               // publish {h1(s), h2(s-1)}
                const int ug = 5 * k + l;
                float* cp = comb + ((size_t)s * 640 + ug) * 2;
                asm volatile("st.volatile.global.v2.f32 [%0], {%1,%2};"
                             :: "l"(cp), "f"(h1val), "f"(h2sh) : "memory");
            }
        }
    }
}

// ---------------- graph prep ----------------
__global__ void zero_deg(int* deg) {
    int i = blockIdx.x * blockDim.x + threadIdx.x;
    if (i < NNODES) deg[i] = 0;
}
__global__ void count_deg(const int* __restrict__ dst, int* deg) {
    int e = blockIdx.x * blockDim.x + threadIdx.x;
    if (e < NEDGES) atomicAdd(&deg[dst[e]], 1);
}
__global__ void finalize_deg(const int* __restrict__ deg, float* dinv, float* selfnorm) {
    int i = blockIdx.x * blockDim.x + threadIdx.x;
    if (i < NNODES) {
        float d = rsqrtf((float)(deg[i] + 1));
        dinv[i] = d;
        selfnorm[i] = d * d;
    }
}
__global__ void edge_norm(const int* __restrict__ src, const int* __restrict__ dst,
                          const float* __restrict__ dinv, float* enorm) {
    int e = blockIdx.x * blockDim.x + threadIdx.x;
    if (e < NEDGES) enorm[e] = dinv[src[e]] * dinv[dst[e]];
}
__global__ void transpose_k(const float* __restrict__ W, float* __restrict__ Wt,
                            int Cin, int Cout) {
    int idx = blockIdx.x * blockDim.x + threadIdx.x;
    if (idx < Cin * Cout) {
        int i = idx / Cout, o = idx % Cout;
        Wt[o * Cin + i] = W[idx];
    }
}

// ---------------- GCN edge scatter ----------------
__global__ void scatter_edges(const float* __restrict__ h, const float* __restrict__ enorm,
                              const int* __restrict__ src, const int* __restrict__ dst,
                              float* __restrict__ y, int C) {
    int idx = blockIdx.x * blockDim.x + threadIdx.x;
    if (idx < NEDGES * C) {
        int e = idx / C, c = idx - e * C;
        atomicAdd(&y[dst[e] * C + c], enorm[e] * h[src[e] * C + c]);
    }
}

// ---------------- bias + leaky + batchnorm (per-column CTA) ----------------
__global__ void bias_leaky_bn(const float* __restrict__ y, const float* __restrict__ b,
                              float* __restrict__ out, int C) {
    const int c = blockIdx.x;
    const int tid = threadIdx.x;
    const float bias = b[c];
    float s = 0.f, sq = 0.f;
    for (int r = tid; r < NNODES; r += 256) {
        float v = y[r * C + c] + bias;
        v = (v > 0.f) ? v : 0.01f * v;
        s += v; sq += v * v;
    }
    __shared__ float rs[256], rq[256];
    rs[tid] = s; rq[tid] = sq;
    __syncthreads();
    for (int o = 128; o > 0; o >>= 1) {
        if (tid < o) { rs[tid] += rs[tid + o]; rq[tid] += rq[tid + o]; }
        __syncthreads();
    }
    float mean = rs[0] * (1.f / NNODES);
    float var = rq[0] * (1.f / NNODES) - mean * mean;
    float rstd = rsqrtf(var + 1e-5f);
    for (int r = tid; r < NNODES; r += 256) {
        float v = y[r * C + c] + bias;
        v = (v > 0.f) ? v : 0.01f * v;
        out[r * C + c] = (v - mean) * rstd;
    }
}

// ---------------- head: segment sum + concat + 3 FC ----------------
__global__ void head_kernel(const float* __restrict__ x,
                            const float* __restrict__ gender, const float* __restrict__ handed,
                            const float* __restrict__ W1, const float* __restrict__ b1,
                            const float* __restrict__ W2, const float* __restrict__ b2,
                            const float* __restrict__ W3, const float* __restrict__ b3,
                            float* __restrict__ out) {
    const int b = blockIdx.x;
    const int tid = threadIdx.x;
    __shared__ float feat[52];
    __shared__ float y1[32], y2[16];
    if (tid < 50) {
        float s = 0.f;
        for (int r = 0; r < 64; r++) s += x[(b * 64 + r) * 50 + tid];
        feat[tid] = s;
    }
    if (tid == 50) feat[50] = gender[b];
    if (tid == 51) feat[51] = handed[b];
    __syncthreads();
    if (tid < 32) {
        float s = b1[tid];
        for (int i = 0; i < 52; i++) s += feat[i] * W1[tid * 52 + i];
        y1[tid] = s;
    }
    __syncthreads();
    if (tid < 16) {
        float s = b2[tid];
        for (int i = 0; i < 32; i++) s += y1[i] * W2[tid * 32 + i];
        y2[tid] = s;
    }
    __syncthreads();
    if (tid == 0) {
        float s = b3[0];
        for (int i = 0; i < 16; i++) s += y2[i] * W3[i];
        out[b] = s;
    }
}

// ---------------- host ----------------
extern "C" void kernel_launch(void* const* d_in, const int* in_sizes, int n_in,
                              void* d_out, int out_size) {
    const float* x_in   = (const float*)d_in[0];
    const int*   eidx   = (const int*)d_in[1];
    const float* gender = (const float*)d_in[2];
    const float* handed = (const float*)d_in[3];
    const float* Wih[3] = {(const float*)d_in[4], (const float*)d_in[8],  (const float*)d_in[12]};
    const float* Whh[3] = {(const float*)d_in[5], (const float*)d_in[9],  (const float*)d_in[13]};
    const float* bih[3] = {(const float*)d_in[6], (const float*)d_in[10], (const float*)d_in[14]};
    const float* bhh[3] = {(const float*)d_in[7], (const float*)d_in[11], (const float*)d_in[15]};
    const float* gcnW[4] = {(const float*)d_in[16], (const float*)d_in[18], (const float*)d_in[20], (const float*)d_in[22]};
    const float* gcnB[4] = {(const float*)d_in[17], (const float*)d_in[19], (const float*)d_in[21], (const float*)d_in[23]};
    const float* fcW[3] = {(const float*)d_in[24], (const float*)d_in[26], (const float*)d_in[28]};
    const float* fcB[3] = {(const float*)d_in[25], (const float*)d_in[27], (const float*)d_in[29]};

    float *xWp, *xW, *bufA, *bufB, *comb, *gh, *gy, *Wt, *dinv, *selfnorm, *enorm;
    int* deg;
    cudaGetSymbolAddress((void**)&xWp, g_xWp);
    cudaGetSymbolAddress((void**)&xW, g_xW);
    cudaGetSymbolAddress((void**)&bufA, g_bufA);
    cudaGetSymbolAddress((void**)&bufB, g_bufB);
    cudaGetSymbolAddress((void**)&comb, g_comb);
    cudaGetSymbolAddress((void**)&gh, g_gh);
    cudaGetSymbolAddress((void**)&gy, g_gy);
    cudaGetSymbolAddress((void**)&Wt, g_Wt);
    cudaGetSymbolAddress((void**)&deg, g_deg);
    cudaGetSymbolAddress((void**)&dinv, g_dinv);
    cudaGetSymbolAddress((void**)&selfnorm, g_selfnorm);
    cudaGetSymbolAddress((void**)&enorm, g_enorm);

    const int* src = eidx;
    const int* dst = eidx + NEDGES;
    dim3 tb(16, 16);
    const int nred = (SEQ * G4) / 4 / 256;            // 2560 CTAs
    const int nfillA = (SEQ * HDIM) / 4 / 256;        // 640 CTAs
    const int ncomb4 = (SEQ * HDIM * 2) / 4;          // 327680 float4s
    const int nfillC = ncomb4 / 256;                  // 1280 CTAs, exact

    // ---- LSTM layer 0: big GEMM (K=8500, split-K s=8) + rec ----
    sgemm128_split<<<dim3(G4 / 128, SEQ / 128, 8), 256>>>(x_in, Wih[0], xWp, SEQ, G4, 8500, 1064);
    reduce_splits<<<nred, 256>>>(xWp, xW, bih[0], bhh[0], 8, G4);
    fill_sentinel_n<<<nfillA, 256>>>(bufA, (SEQ * HDIM) / 4);
    lstm_rec<<<NCTA_REC, 640>>>(xW, Whh[0], bufA);            // h0 -> bufA

    // ---- layer-1 input projection (K=640, split-K s=2) ----
    sgemm128_split<<<dim3(G4 / 128, SEQ / 128, 2), 256>>>(bufA, Wih[1], xWp, SEQ, G4, HDIM, 320);
    reduce_splits<<<nred, 256>>>(xWp, xW, bih[1], bhh[1], 2, G4);

    // ---- wavefront: layers 1+2 pipelined (L2 GEMM eliminated) ----
    fill_sentinel_n<<<nfillC, 256>>>(comb, ncomb4);
    lstm_wave12<<<NCTA_REC, 640>>>(xW, Whh[1], Wih[2], Whh[2], bih[2], bhh[2],
                                   comb, bufB);               // h2 -> bufB

    // ---- graph prep ----
    zero_deg<<<4, 256>>>(deg);
    count_deg<<<NEDGES / 256, 256>>>(dst, deg);
    finalize_deg<<<4, 256>>>(deg, dinv, selfnorm);
    edge_norm<<<NEDGES / 256, 256>>>(src, dst, dinv, enorm);

    // ---- GCN layers (self-loop term fused into GEMM epilogue) ----
    const int cins[4]  = {640, 320, 180, 90};
    const int couts[4] = {320, 180, 90, 50};
    float* xcur = bufB;
    float* xnext = bufA;
    for (int l = 0; l < 4; l++) {
        int Cin = cins[l], Cout = couts[l];
        transpose_k<<<(Cin * Cout + 255) / 256, 256>>>(gcnW[l], Wt, Cin, Cout);
        sgemm_nt_gcn<<<dim3((Cout + 63) / 64, NNODES / 128), tb>>>(xcur, Wt, selfnorm,
                                                                   gh, gy, NNODES, Cout, Cin);
        scatter_edges<<<(NEDGES * Cout + 255) / 256, 256>>>(gh, enorm, src, dst, gy, Cout);
        bias_leaky_bn<<<Cout, 256>>>(gy, gcnB[l], xnext, Cout);
        float* tmp = xcur; xcur = xnext; xnext = tmp;
    }

    // ---- head ----
    head_kernel<<<BSZ, 64>>>(xcur, gender, handed,
                             fcW[0], fcB[0], fcW[1], fcB[1], fcW[2], fcB[2],
                             (float*)d_out);
}

// round 14
// speedup vs baseline: 2.4175x; 1.3207x over previous
#include <cuda_runtime.h>

#define SEQ     1024
#define HDIM    640
#define G4      2560
#define NNODES  1024
#define NEDGES  16384
#define BSZ     16
#define NCTA_REC 128
#define MAXSPLIT 8
#define SENTINEL_U 0x40000000u   /* 2.0f — impossible for |h|<1 */

// ---------------- scratch (device globals; no runtime allocation) ----------------
__device__ float g_xWp[MAXSPLIT][SEQ * G4]; // 84 MB  split-K partials
__device__ float g_xW[SEQ * G4];            // 10.5 MB reduced L0 input projections
__device__ float g_bufA[SEQ * HDIM];
__device__ float g_bufB[SEQ * HDIM];
__device__ float g_comb4[(SEQ + 1) * HDIM * 4]; // float4 {h0(s),h1(s-1),h2(s-2),0}
__device__ float g_gh[NNODES * 320];
__device__ float g_gy[NNODES * 320];
__device__ float g_Wt[640 * 320];
__device__ int   g_deg[NNODES];
__device__ float g_dinv[NNODES];
__device__ float g_selfnorm[NNODES];
__device__ float g_enorm[NEDGES];

__device__ __forceinline__ float fsigmoid(float x) { return 1.f / (1.f + __expf(-x)); }
__device__ __forceinline__ float ftanh(float x) { return 2.f / (1.f + __expf(-2.f * x)) - 1.f; }

// ---------------- split-K fp32 NT GEMM: partial C_z = A[:,kz]*B[:,kz]^T ----------------
__global__ __launch_bounds__(256) void sgemm128_split(
    const float* __restrict__ A, const float* __restrict__ B,
    float* __restrict__ Cbase, int M, int N, int K, int Kc)
{
    __shared__ float As[2][16][128];
    __shared__ float Bs[2][16][128];
    const int tid = threadIdx.x;
    const int z = blockIdx.z;
    const int k0 = z * Kc;
    const int kend = min(K, k0 + Kc);
    float* __restrict__ C = Cbase + (size_t)z * ((size_t)SEQ * G4);
    const int m0 = blockIdx.y * 128, n0 = blockIdx.x * 128;
    const int rowg = (tid >> 4) << 3;
    const int colg = (tid & 15) << 3;

    float acc[8][8];
#pragma unroll
    for (int i = 0; i < 8; i++)
#pragma unroll
        for (int j = 0; j < 8; j++) acc[i][j] = 0.f;

    const int ntiles = (kend - k0 + 15) >> 4;

    auto ldtile = [&](const float* __restrict__ P, int base_row, int kb, float4* out) {
#pragma unroll
        for (int i = 0; i < 2; i++) {
            int fid = tid * 2 + i;
            int r = fid >> 2, kk = (fid & 3) << 2;
            float4 v = make_float4(0.f, 0.f, 0.f, 0.f);
            const float* p = P + (size_t)(base_row + r) * K + kb + kk;
            if (kb + kk + 3 < kend) v = *(const float4*)p;
            else {
                if (kb + kk + 0 < kend) v.x = p[0];
                if (kb + kk + 1 < kend) v.y = p[1];
                if (kb + kk + 2 < kend) v.z = p[2];
            }
            out[i] = v;
        }
    };
    auto sttile = [&](float (*S)[128], const float4* v) {
#pragma unroll
        for (int i = 0; i < 2; i++) {
            int fid = tid * 2 + i;
            int r = fid >> 2, kk = (fid & 3) << 2;
            S[kk + 0][r] = v[i].x; S[kk + 1][r] = v[i].y;
            S[kk + 2][r] = v[i].z; S[kk + 3][r] = v[i].w;
        }
    };

    float4 pa[2], pb[2];
    ldtile(A, m0, k0, pa);
    ldtile(B, n0, k0, pb);
    sttile(As[0], pa);
    sttile(Bs[0], pb);
    __syncthreads();

    for (int kt = 0; kt < ntiles; kt++) {
        const int cur = kt & 1;
        if (kt + 1 < ntiles) {
            ldtile(A, m0, k0 + (kt + 1) * 16, pa);
            ldtile(B, n0, k0 + (kt + 1) * 16, pb);
        }
        const float (*Ac)[128] = As[cur];
        const float (*Bc)[128] = Bs[cur];
#pragma unroll
        for (int k = 0; k < 16; k++) {
            float4 a0 = *(const float4*)&Ac[k][rowg];
            float4 a1 = *(const float4*)&Ac[k][rowg + 4];
            float4 b0 = *(const float4*)&Bc[k][colg];
            float4 b1 = *(const float4*)&Bc[k][colg + 4];
            float a[8]  = {a0.x, a0.y, a0.z, a0.w, a1.x, a1.y, a1.z, a1.w};
            float bb[8] = {b0.x, b0.y, b0.z, b0.w, b1.x, b1.y, b1.z, b1.w};
#pragma unroll
            for (int i = 0; i < 8; i++)
#pragma unroll
                for (int j = 0; j < 8; j++)
                    acc[i][j] += a[i] * bb[j];
        }
        if (kt + 1 < ntiles) {
            sttile(As[1 - cur], pa);
            sttile(Bs[1 - cur], pb);
        }
        __syncthreads();
    }

#pragma unroll
    for (int i = 0; i < 8; i++) {
        const int m = m0 + rowg + i;
        float* cp = C + (size_t)m * N + n0 + colg;
#pragma unroll
        for (int j = 0; j < 8; j++) cp[j] = acc[i][j];
    }
}

// ---------------- sum split partials + fold biases ----------------
__global__ void reduce_splits(const float* __restrict__ bufs, float* __restrict__ C,
                              const float* __restrict__ b1, const float* __restrict__ b2,
                              int s, int N)
{
    int idx = blockIdx.x * blockDim.x + threadIdx.x;
    size_t base = (size_t)idx * 4;
    float4 acc = *(const float4*)(bufs + base);
    for (int i = 1; i < s; i++) {
        float4 v = *(const float4*)(bufs + (size_t)i * ((size_t)SEQ * G4) + base);
        acc.x += v.x; acc.y += v.y; acc.z += v.z; acc.w += v.w;
    }
    int n = (int)(base % (size_t)N);
    float4 u1 = *(const float4*)(b1 + n);
    float4 u2 = *(const float4*)(b2 + n);
    acc.x += u1.x + u2.x; acc.y += u1.y + u2.y;
    acc.z += u1.z + u2.z; acc.w += u1.w + u2.w;
    *(float4*)(C + base) = acc;
}

// ---------------- GCN fp32 NT GEMM with fused self-loop epilogue ----------------
__global__ __launch_bounds__(256) void sgemm_nt_gcn(
    const float* __restrict__ A, const float* __restrict__ B,
    const float* __restrict__ selfnorm,
    float* __restrict__ GH, float* __restrict__ GY, int M, int N, int K)
{
    __shared__ float As[16][128];
    __shared__ float Bs[16][64];
    const int tx = threadIdx.x, ty = threadIdx.y;
    const int tid = ty * 16 + tx;
    const int m0 = blockIdx.y * 128, n0 = blockIdx.x * 64;

    float acc[8][4];
#pragma unroll
    for (int i = 0; i < 8; i++)
#pragma unroll
        for (int j = 0; j < 4; j++) acc[i][j] = 0.f;

    const bool k4ok = ((K & 3) == 0);
    const int ntiles = (K + 15) >> 4;

    for (int kt = 0; kt < ntiles; kt++) {
        const int kb = kt * 16;
#pragma unroll
        for (int i = 0; i < 2; i++) {
            int fid = tid * 2 + i;
            int r = fid >> 2;
            int kk = (fid & 3) << 2;
            float4 v = make_float4(0.f, 0.f, 0.f, 0.f);
            if (m0 + r < M) {
                const float* ap = A + (size_t)(m0 + r) * K + kb + kk;
                if (k4ok && kb + kk + 3 < K) v = *(const float4*)ap;
                else {
                    if (kb + kk + 0 < K) v.x = ap[0];
                    if (kb + kk + 1 < K) v.y = ap[1];
                    if (kb + kk + 2 < K) v.z = ap[2];
                    if (kb + kk + 3 < K) v.w = ap[3];
                }
            }
            As[kk + 0][r] = v.x; As[kk + 1][r] = v.y;
            As[kk + 2][r] = v.z; As[kk + 3][r] = v.w;
        }
        {
            int r = tid >> 2;
            int kk = (tid & 3) << 2;
            float4 v = make_float4(0.f, 0.f, 0.f, 0.f);
            if (n0 + r < N) {
                const float* bp = B + (size_t)(n0 + r) * K + kb + kk;
                if (k4ok && kb + kk + 3 < K) v = *(const float4*)bp;
                else {
                    if (kb + kk + 0 < K) v.x = bp[0];
                    if (kb + kk + 1 < K) v.y = bp[1];
                    if (kb + kk + 2 < K) v.z = bp[2];
                    if (kb + kk + 3 < K) v.w = bp[3];
                }
            }
            Bs[kk + 0][r] = v.x; Bs[kk + 1][r] = v.y;
            Bs[kk + 2][r] = v.z; Bs[kk + 3][r] = v.w;
        }
        __syncthreads();
#pragma unroll
        for (int k = 0; k < 16; k++) {
            float4 b4 = *(const float4*)&Bs[k][tx * 4];
            float4 a0 = *(const float4*)&As[k][ty * 8];
            float4 a1 = *(const float4*)&As[k][ty * 8 + 4];
            float a[8] = {a0.x, a0.y, a0.z, a0.w, a1.x, a1.y, a1.z, a1.w};
            float bb[4] = {b4.x, b4.y, b4.z, b4.w};
#pragma unroll
            for (int i = 0; i < 8; i++)
#pragma unroll
                for (int j = 0; j < 4; j++)
                    acc[i][j] += a[i] * bb[j];
        }
        __syncthreads();
    }
#pragma unroll
    for (int i = 0; i < 8; i++) {
        int m = m0 + ty * 8 + i;
        if (m >= M) continue;
        const float sn = selfnorm[m];
#pragma unroll
        for (int j = 0; j < 4; j++) {
            int n = n0 + tx * 4 + j;
            if (n < N) {
                float v = acc[i][j];
                GH[(size_t)m * N + n] = v;
                GY[(size_t)m * N + n] = sn * v;
            }
        }
    }
}

// ---------------- sentinel fill (n4 float4s) ----------------
__global__ void fill_sentinel_n(float* __restrict__ p, int n4) {
    int i = blockIdx.x * blockDim.x + threadIdx.x;
    if (i < n4) ((float4*)p)[i] = make_float4(2.f, 2.f, 2.f, 2.f);
}

// ---------------- 3-layer wavefront recurrence ----------------
// Step s (0..SEQ+1): L0 computes h0(s) [s<SEQ], L1 computes h1(s-1) [1<=s<=SEQ],
// L2 computes h2(s-2) [2<=s<=SEQ+1]. Channel comb4[s][j] = {h0(s),h1(s-1),h2(s-2),0}:
// ONE 16B volatile v4 poll per thread per step (R9-calibrated request density).
// Weights: Whh0/Wih1/Whh1 register-resident (20 each); Wih2/Whh2 in dynamic smem,
// bank-swizzled so the per-lane scalar LDS stream is conflict-free.
// Warp-0 lanes: 0-4 L0 gates (c0), 8-12 L1 gates (c1), 16-20 L2 gates (c2).
__global__ __launch_bounds__(640, 1) void lstm_wave012(
    const float* __restrict__ xW0,   // [1024,2560] L0 input projection (biases folded)
    const float* __restrict__ Whh0,
    const float* __restrict__ Wih1, const float* __restrict__ Whh1,
    const float* __restrict__ bih1, const float* __restrict__ bhh1,
    const float* __restrict__ Wih2, const float* __restrict__ Whh2,
    const float* __restrict__ bih2, const float* __restrict__ bhh2,
    float* __restrict__ comb4,       // [(SEQ+1)*640] float4, sentinel-filled
    float* __restrict__ h2out)       // [1024,640] plain layer-2 output
{
    extern __shared__ float sm[];
    float* h0_s  = sm;                 // 640
    float* h1_s  = sm + 640;           // 640
    float* h2_s  = sm + 1280;          // 640
    float* dots0 = sm + 1920;          // 20 (index w = u*4+gsel)
    float* dots1 = sm + 1940;          // 20
    float* dots2 = sm + 1960;          // 20
    float* wI2_s = sm + 1984;          // 20*640 swizzled
    float* wH2_s = wI2_s + 12800;      // 20*640 swizzled

    const int tid = threadIdx.x;
    const int w = tid >> 5, l = tid & 31;
    const int k = blockIdx.x;
    const int u = w >> 2;
    const int gsel = w & 3;
    const int uglob = 5 * k + u;
    const int row = gsel * 640 + uglob;

    // register slices (60 regs)
    float wr0[20], wI1[20], wH1[20];
    {
        const float* p0 = Whh0 + (size_t)row * 640 + 20 * l;
        const float* p1 = Wih1 + (size_t)row * 640 + 20 * l;
        const float* p2 = Whh1 + (size_t)row * 640 + 20 * l;
#pragma unroll
        for (int i = 0; i < 20; i++) wr0[i] = p0[i];
#pragma unroll
        for (int i = 0; i < 20; i++) wI1[i] = p1[i];
#pragma unroll
        for (int i = 0; i < 20; i++) wH1[i] = p2[i];
    }

    // smem slices, bank-swizzled: sm[j*640 + i*32 + lane] = W[row_j][20*lane + i]
    for (int idx = tid; idx < 12800; idx += 640) {
        int j = idx / 640;
        int e = idx - j * 640;
        int lane = e & 31, ii = e >> 5;
        int col = 20 * lane + ii;
        int rowj = (j & 3) * 640 + 5 * k + (j >> 2);
        wI2_s[idx] = Wih2[(size_t)rowj * 640 + col];
        wH2_s[idx] = Whh2[(size_t)rowj * 640 + col];
    }

    // states + biases in warp-0 lane registers
    float c0 = 0.f, c1 = 0.f, c2 = 0.f;
    float b0r = 0.f, b1r = 0.f, b2r = 0.f, b3r = 0.f;   // per-lane 4 gate biases
    if (w == 0) {
        if (l >= 8 && l < 13) {
            int ug = 5 * k + (l - 8);
            b0r = bih1[ug]        + bhh1[ug];
            b1r = bih1[640 + ug]  + bhh1[640 + ug];
            b2r = bih1[1280 + ug] + bhh1[1280 + ug];
            b3r = bih1[1920 + ug] + bhh1[1920 + ug];
        } else if (l >= 16 && l < 21) {
            int ug = 5 * k + (l - 16);
            b0r = bih2[ug]        + bhh2[ug];
            b1r = bih2[640 + ug]  + bhh2[640 + ug];
            b2r = bih2[1280 + ug] + bhh2[1280 + ug];
            b3r = bih2[1920 + ug] + bhh2[1920 + ug];
        }
    }
    __syncthreads();

    const float* wI2r = wI2_s + w * 640 + l;
    const float* wH2r = wH2_s + w * 640 + l;

    for (int s = 0; s <= SEQ + 1; s++) {
        // L0 gate lanes prefetch xW0 operands (off critical path)
        float xg0 = 0.f, xg1 = 0.f, xg2 = 0.f, xg3 = 0.f;
        if (tid < 5 && s < SEQ) {
            const float* xwt = xW0 + (size_t)s * G4 + 5 * k + tid;
            xg0 = __ldg(xwt);
            xg1 = __ldg(xwt + 640);
            xg2 = __ldg(xwt + 1280);
            xg3 = __ldg(xwt + 1920);
        }

        float acc0 = 0.f, acc1 = 0.f, acc2 = 0.f;
        if (s > 0) {
            // single v4 sentinel poll per thread (calibrated density: 1 req/thread/RT)
            const float* cp = comb4 + ((size_t)(s - 1) * 640 + tid) * 4;
            float hx, hy, hz, hw_;
            do {
                asm volatile("ld.volatile.global.v4.f32 {%0,%1,%2,%3}, [%4];"
                             : "=f"(hx), "=f"(hy), "=f"(hz), "=f"(hw_)
                             : "l"(cp) : "memory");
            } while (__float_as_uint(hx) == SENTINEL_U ||
                     __float_as_uint(hy) == SENTINEL_U ||
                     __float_as_uint(hz) == SENTINEL_U);
            h0_s[tid] = hx;    // h0(s-1)
            h1_s[tid] = hy;    // h1(s-2)
            h2_s[tid] = hz;    // h2(s-3)
            __syncthreads();
            const float4* p0 = (const float4*)(h0_s + 20 * l);
            const float4* p1 = (const float4*)(h1_s + 20 * l);
            const float4* p2 = (const float4*)(h2_s + 20 * l);
#pragma unroll
            for (int ii = 0; ii < 5; ii++) {
                float4 v0 = p0[ii];
                float4 v1 = p1[ii];
                float4 v2 = p2[ii];
                acc0 += wr0[4 * ii + 0] * v0.x + wr0[4 * ii + 1] * v0.y
                      + wr0[4 * ii + 2] * v0.z + wr0[4 * ii + 3] * v0.w;
                acc1 += wI1[4 * ii + 0] * v0.x + wI1[4 * ii + 1] * v0.y
                      + wI1[4 * ii + 2] * v0.z + wI1[4 * ii + 3] * v0.w
                      + wH1[4 * ii + 0] * v1.x + wH1[4 * ii + 1] * v1.y
                      + wH1[4 * ii + 2] * v1.z + wH1[4 * ii + 3] * v1.w;
                acc2 += wI2r[(4 * ii + 0) * 32] * v1.x + wI2r[(4 * ii + 1) * 32] * v1.y
                      + wI2r[(4 * ii + 2) * 32] * v1.z + wI2r[(4 * ii + 3) * 32] * v1.w
                      + wH2r[(4 * ii + 0) * 32] * v2.x + wH2r[(4 * ii + 1) * 32] * v2.y
                      + wH2r[(4 * ii + 2) * 32] * v2.z + wH2r[(4 * ii + 3) * 32] * v2.w;
            }
        }
#pragma unroll
        for (int off = 16; off > 0; off >>= 1) {
            acc0 += __shfl_down_sync(0xffffffffu, acc0, off);
            acc1 += __shfl_down_sync(0xffffffffu, acc1, off);
            acc2 += __shfl_down_sync(0xffffffffu, acc2, off);
        }
        if (l == 0) { dots0[w] = acc0; dots1[w] = acc1; dots2[w] = acc2; }
        __syncthreads();

        if (w == 0) {
            float h0val = 0.f, h1val = 0.f, h2val = 0.f;
            if (l < 5 && s < SEQ) {                       // L0: h0(s)
                const int uu = l;
                float gi = xg0 + dots0[uu * 4 + 0];
                float gf = xg1 + dots0[uu * 4 + 1];
                float gg = xg2 + dots0[uu * 4 + 2];
                float go = xg3 + dots0[uu * 4 + 3];
                float iv = fsigmoid(gi), fv = fsigmoid(gf);
                float gv = ftanh(gg),   ov = fsigmoid(go);
                c0 = fv * c0 + iv * gv;
                h0val = ov * ftanh(c0);
            }
            if (l >= 8 && l < 13 && s >= 1 && s <= SEQ) { // L1: h1(s-1)
                const int uu = l - 8;
                float gi = b0r + dots1[uu * 4 + 0];
                float gf = b1r + dots1[uu * 4 + 1];
                float gg = b2r + dots1[uu * 4 + 2];
                float go = b3r + dots1[uu * 4 + 3];
                float iv = fsigmoid(gi), fv = fsigmoid(gf);
                float gv = ftanh(gg),   ov = fsigmoid(go);
                c1 = fv * c1 + iv * gv;
                h1val = ov * ftanh(c1);
            }
            if (l >= 16 && l < 21 && s >= 2) {            // L2: h2(s-2)
                const int uu = l - 16;
                const int ug = 5 * k + uu;
                float gi = b0r + dots2[uu * 4 + 0];
                float gf = b1r + dots2[uu * 4 + 1];
                float gg = b2r + dots2[uu * 4 + 2];
                float go = b3r + dots2[uu * 4 + 3];
                float iv = fsigmoid(gi), fv = fsigmoid(gf);
                float gv = ftanh(gg),   ov = fsigmoid(go);
                c2 = fv * c2 + iv * gv;
                h2val = ov * ftanh(c2);
                h2out[(size_t)(s - 2) * 640 + ug] = h2val;  // plain store for GCN
            }
            // lanes 0-4 gather h1(s-1) from lanes 8-12, h2(s-2) from lanes 16-20
            float h1sh = __shfl_sync(0xffffffffu, h1val, (l + 8) & 31);
            float h2sh = __shfl_sync(0xffffffffu, h2val, (l + 16) & 31);
            if (l < 5 && s <= SEQ) {                      // publish triple
                const int ug = 5 * k + l;
                float* cp = comb4 + ((size_t)s * 640 + ug) * 4;
                asm volatile("st.volatile.global.v4.f32 [%0], {%1,%2,%3,%4};"
                             :: "l"(cp), "f"(h0val), "f"(h1sh), "f"(h2sh), "f"(0.f)
                             : "memory");
            }
        }
    }
}

// ---------------- graph prep ----------------
__global__ void zero_deg(int* deg) {
    int i = blockIdx.x * blockDim.x + threadIdx.x;
    if (i < NNODES) deg[i] = 0;
}
__global__ void count_deg(const int* __restrict__ dst, int* deg) {
    int e = blockIdx.x * blockDim.x + threadIdx.x;
    if (e < NEDGES) atomicAdd(&deg[dst[e]], 1);
}
__global__ void finalize_deg(const int* __restrict__ deg, float* dinv, float* selfnorm) {
    int i = blockIdx.x * blockDim.x + threadIdx.x;
    if (i < NNODES) {
        float d = rsqrtf((float)(deg[i] + 1));
        dinv[i] = d;
        selfnorm[i] = d * d;
    }
}
__global__ void edge_norm(const int* __restrict__ src, const int* __restrict__ dst,
                          const float* __restrict__ dinv, float* enorm) {
    int e = blockIdx.x * blockDim.x + threadIdx.x;
    if (e < NEDGES) enorm[e] = dinv[src[e]] * dinv[dst[e]];
}
__global__ void transpose_k(const float* __restrict__ W, float* __restrict__ Wt,
                            int Cin, int Cout) {
    int idx = blockIdx.x * blockDim.x + threadIdx.x;
    if (idx < Cin * Cout) {
        int i = idx / Cout, o = idx % Cout;
        Wt[o * Cin + i] = W[idx];
    }
}

// ---------------- GCN edge scatter ----------------
__global__ void scatter_edges(const float* __restrict__ h, const float* __restrict__ enorm,
                              const int* __restrict__ src, const int* __restrict__ dst,
                              float* __restrict__ y, int C) {
    int idx = blockIdx.x * blockDim.x + threadIdx.x;
    if (idx < NEDGES * C) {
        int e = idx / C, c = idx - e * C;
        atomicAdd(&y[dst[e] * C + c], enorm[e] * h[src[e] * C + c]);
    }
}

// ---------------- bias + leaky + batchnorm (per-column CTA) ----------------
__global__ void bias_leaky_bn(const float* __restrict__ y, const float* __restrict__ b,
                              float* __restrict__ out, int C) {
    const int c = blockIdx.x;
    const int tid = threadIdx.x;
    const float bias = b[c];
    float s = 0.f, sq = 0.f;
    for (int r = tid; r < NNODES; r += 256) {
        float v = y[r * C + c] + bias;
        v = (v > 0.f) ? v : 0.01f * v;
        s += v; sq += v * v;
    }
    __shared__ float rs[256], rq[256];
    rs[tid] = s; rq[tid] = sq;
    __syncthreads();
    for (int o = 128; o > 0; o >>= 1) {
        if (tid < o) { rs[tid] += rs[tid + o]; rq[tid] += rq[tid + o]; }
        __syncthreads();
    }
    float mean = rs[0] * (1.f / NNODES);
    float var = rq[0] * (1.f / NNODES) - mean * mean;
    float rstd = rsqrtf(var + 1e-5f);
    for (int r = tid; r < NNODES; r += 256) {
        float v = y[r * C + c] + bias;
        v = (v > 0.f) ? v : 0.01f * v;
        out[r * C + c] = (v - mean) * rstd;
    }
}

// ---------------- head: segment sum + concat + 3 FC ----------------
__global__ void head_kernel(const float* __restrict__ x,
                            const float* __restrict__ gender, const float* __restrict__ handed,
                            const float* __restrict__ W1, const float* __restrict__ b1,
                            const float* __restrict__ W2, const float* __restrict__ b2,
                            const float* __restrict__ W3, const float* __restrict__ b3,
                            float* __restrict__ out) {
    const int b = blockIdx.x;
    const int tid = threadIdx.x;
    __shared__ float feat[52];
    __shared__ float y1[32], y2[16];
    if (tid < 50) {
        float s = 0.f;
        for (int r = 0; r < 64; r++) s += x[(b * 64 + r) * 50 + tid];
        feat[tid] = s;
    }
    if (tid == 50) feat[50] = gender[b];
    if (tid == 51) feat[51] = handed[b];
    __syncthreads();
    if (tid < 32) {
        float s = b1[tid];
        for (int i = 0; i < 52; i++) s += feat[i] * W1[tid * 52 + i];
        y1[tid] = s;
    }
    __syncthreads();
    if (tid < 16) {
        float s = b2[tid];
        for (int i = 0; i < 32; i++) s += y1[i] * W2[tid * 32 + i];
        y2[tid] = s;
    }
    __syncthreads();
    if (tid == 0) {
        float s = b3[0];
        for (int i = 0; i < 16; i++) s += y2[i] * W3[i];
        out[b] = s;
    }
}

// ---------------- host ----------------
extern "C" void kernel_launch(void* const* d_in, const int* in_sizes, int n_in,
                              void* d_out, int out_size) {
    const float* x_in   = (const float*)d_in[0];
    const int*   eidx   = (const int*)d_in[1];
    const float* gender = (const float*)d_in[2];
    const float* handed = (const float*)d_in[3];
    const float* Wih[3] = {(const float*)d_in[4], (const float*)d_in[8],  (const float*)d_in[12]};
    const float* Whh[3] = {(const float*)d_in[5], (const float*)d_in[9],  (const float*)d_in[13]};
    const float* bih[3] = {(const float*)d_in[6], (const float*)d_in[10], (const float*)d_in[14]};
    const float* bhh[3] = {(const float*)d_in[7], (const float*)d_in[11], (const float*)d_in[15]};
    const float* gcnW[4] = {(const float*)d_in[16], (const float*)d_in[18], (const float*)d_in[20], (const float*)d_in[22]};
    const float* gcnB[4] = {(const float*)d_in[17], (const float*)d_in[19], (const float*)d_in[21], (const float*)d_in[23]};
    const float* fcW[3] = {(const float*)d_in[24], (const float*)d_in[26], (const float*)d_in[28]};
    const float* fcB[3] = {(const float*)d_in[25], (const float*)d_in[27], (const float*)d_in[29]};

    float *xWp, *xW, *bufA, *bufB, *comb4, *gh, *gy, *Wt, *dinv, *selfnorm, *enorm;
    int* deg;
    cudaGetSymbolAddress((void**)&xWp, g_xWp);
    cudaGetSymbolAddress((void**)&xW, g_xW);
    cudaGetSymbolAddress((void**)&bufA, g_bufA);
    cudaGetSymbolAddress((void**)&bufB, g_bufB);
    cudaGetSymbolAddress((void**)&comb4, g_comb4);
    cudaGetSymbolAddress((void**)&gh, g_gh);
    cudaGetSymbolAddress((void**)&gy, g_gy);
    cudaGetSymbolAddress((void**)&Wt, g_Wt);
    cudaGetSymbolAddress((void**)&deg, g_deg);
    cudaGetSymbolAddress((void**)&dinv, g_dinv);
    cudaGetSymbolAddress((void**)&selfnorm, g_selfnorm);
    cudaGetSymbolAddress((void**)&enorm, g_enorm);

    const int* src = eidx;
    const int* dst = eidx + NEDGES;
    dim3 tb(16, 16);
    const int nred = (SEQ * G4) / 4 / 256;                    // 2560 CTAs
    const int ncomb4 = ((SEQ + 1) * HDIM * 4) / 4;            // 656000 float4s
    const int nfillC = (ncomb4 + 255) / 256;

    const int WAVE_SMEM = (1984 + 2 * 12800) * 4;             // 110336 B dynamic
    cudaFuncSetAttribute(lstm_wave012, cudaFuncAttributeMaxDynamicSharedMemorySize, WAVE_SMEM);

    // ---- L0 input projection (K=8500, split-K s=8, Kc=1064) ----
    sgemm128_split<<<dim3(G4 / 128, SEQ / 128, 8), 256>>>(x_in, Wih[0], xWp, SEQ, G4, 8500, 1064);
    reduce_splits<<<nred, 256>>>(xWp, xW, bih[0], bhh[0], 8, G4);

    // ---- 3-layer wavefront: rec0 + L1 GEMM + rec1 + L2 GEMM + rec2, all fused ----
    fill_sentinel_n<<<nfillC, 256>>>(comb4, ncomb4);
    lstm_wave012<<<NCTA_REC, 640, WAVE_SMEM>>>(xW, Whh[0],
                                               Wih[1], Whh[1], bih[1], bhh[1],
                                               Wih[2], Whh[2], bih[2], bhh[2],
                                               comb4, bufB);      // h2 -> bufB

    // ---- graph prep ----
    zero_deg<<<4, 256>>>(deg);
    count_deg<<<NEDGES / 256, 256>>>(dst, deg);
    finalize_deg<<<4, 256>>>(deg, dinv, selfnorm);
    edge_norm<<<NEDGES / 256, 256>>>(src, dst, dinv, enorm);

    // ---- GCN layers (self-loop term fused into GEMM epilogue) ----
    const int cins[4]  = {640, 320, 180, 90};
    const int couts[4] = {320, 180, 90, 50};
    float* xcur = bufB;
    float* xnext = bufA;
    for (int l = 0; l < 4; l++) {
        int Cin = cins[l], Cout = couts[l];
        transpose_k<<<(Cin * Cout + 255) / 256, 256>>>(gcnW[l], Wt, Cin, Cout);
        sgemm_nt_gcn<<<dim3((Cout + 63) / 64, NNODES / 128), tb>>>(xcur, Wt, selfnorm,
                                                                   gh, gy, NNODES, Cout, Cin);
        scatter_edges<<<(NEDGES * Cout + 255) / 256, 256>>>(gh, enorm, src, dst, gy, Cout);
        bias_leaky_bn<<<Cout, 256>>>(gy, gcnB[l], xnext, Cout);
        float* tmp = xcur; xcur = xnext; xnext = tmp;
    }

    // ---- head ----
    head_kernel<<<BSZ, 64>>>(xcur, gender, handed,
                             fcW[0], fcB[0], fcW[1], fcB[1], fcW[2], fcB[2],
                             (float*)d_out);
}